// round 1
// baseline (speedup 1.0000x reference)
#include <cuda_runtime.h>

#define BATCH 16
#define NSEQ  1024      // sparse tokens per batch
#define NTOK  2048      // total tokens per batch
#define DM    256
#define NLAYER 4
#define NSTATE 8
#define NF    16
#define CIN   33
#define LN_EPS 1e-5f

// ---------------- scratch (device globals; no allocation) ----------------
__device__ float g_seq [BATCH*NTOK*DM];
__device__ float g_xn  [BATCH*NTOK*DM];
__device__ float g_gate[BATCH*NTOK*DM];
__device__ float g_bu  [BATCH*NTOK*NSTATE];
__device__ float g_hs  [BATCH*NTOK*NSTATE];
__device__ float g_q   [BATCH*NSEQ*DM];
__device__ float g_k   [BATCH*NSEQ*DM];
__device__ float g_v   [BATCH*NSEQ*DM];
__device__ float g_att [BATCH*NSEQ*DM];
__device__ float g_x1  [BATCH*NSEQ*DM];
__device__ float g_h   [BATCH*NSEQ*DM];

// ---------------- embed: fourier + input proj + time embed ----------------
__global__ void embed_kernel(const float* __restrict__ sparse_coords,
                             const float* __restrict__ sparse_values,
                             const float* __restrict__ query_coords,
                             const float* __restrict__ t_in,
                             const float* __restrict__ noise,
                             const float* __restrict__ B_f,
                             const float* __restrict__ Wq, const float* __restrict__ bq,
                             const float* __restrict__ Wi, const float* __restrict__ bi,
                             float* __restrict__ seq)
{
    int token = blockIdx.x;            // 0 .. B*NTOK-1
    int b = token / NTOK;
    int n = token % NTOK;
    int tid = threadIdx.x;

    __shared__ float feat[CIN];
    const float* W;
    const float* bias;
    float cx, cy, val;
    if (n < NSEQ) {
        cx = sparse_coords[(b*NSEQ + n)*2 + 0];
        cy = sparse_coords[(b*NSEQ + n)*2 + 1];
        val = sparse_values[b*NSEQ + n];
        W = Wi; bias = bi;
    } else {
        int m = n - NSEQ;
        cx = query_coords[(b*NSEQ + m)*2 + 0];
        cy = query_coords[(b*NSEQ + m)*2 + 1];
        val = noise[b*NSEQ + m];
        W = Wq; bias = bq;
    }
    if (tid < NF) {
        float proj = cx * B_f[tid] + cy * B_f[NF + tid];
        feat[tid]      = sinf(proj);
        feat[NF + tid] = cosf(proj);
    }
    if (tid == 0) feat[2*NF] = val;
    __syncthreads();

    int d = tid;                    // 0..255
    float acc = bias[d];
    const float* wrow = W + d*CIN;
    #pragma unroll
    for (int k = 0; k < CIN; k++) acc += feat[k] * wrow[k];

    // time embedding: half=128, freqs = exp(i * -ln(10000)/127)
    float tv = t_in[b];
    float e;
    if (d < 128) e = sinf(tv * expf((float)d * (-9.210340371976184f / 127.f)));
    else         e = cosf(tv * expf((float)(d-128) * (-9.210340371976184f / 127.f)));

    seq[token*DM + d] = acc + e;
}

// ---------------- layernorm + Bu = xn @ Bw^T  ----------------
__global__ void ln_bu_kernel(const float* __restrict__ lng, const float* __restrict__ lnb,
                             const float* __restrict__ Bw,
                             const float* __restrict__ seq,
                             float* __restrict__ xn_out, float* __restrict__ bu_out)
{
    int token = blockIdx.x;
    int tid = threadIdx.x;
    __shared__ float xs[DM];
    __shared__ float red[DM];

    float x = seq[token*DM + tid];
    red[tid] = x; __syncthreads();
    for (int s = 128; s > 0; s >>= 1) { if (tid < s) red[tid] += red[tid + s]; __syncthreads(); }
    float mu = red[0] * (1.f/256.f);
    __syncthreads();
    float dx = x - mu;
    red[tid] = dx*dx; __syncthreads();
    for (int s = 128; s > 0; s >>= 1) { if (tid < s) red[tid] += red[tid + s]; __syncthreads(); }
    float var = red[0] * (1.f/256.f);

    float xn = dx * rsqrtf(var + LN_EPS) * lng[tid] + lnb[tid];
    xn_out[token*DM + tid] = xn;
    xs[tid] = xn;
    __syncthreads();

    int w = tid >> 5, lane = tid & 31;   // 8 warps -> 8 states
    float s = 0.f;
    #pragma unroll
    for (int i = 0; i < 8; i++) {
        int d = lane + i*32;
        s += xs[d] * Bw[w*DM + d];
    }
    #pragma unroll
    for (int off = 16; off; off >>= 1) s += __shfl_down_sync(0xffffffffu, s, off);
    if (lane == 0) bu_out[token*NSTATE + w] = s;
}

// ---------------- parallel linear-recurrence scan (exact associative op) ----
__global__ void scan_kernel(const float* __restrict__ A_log,
                            const float* __restrict__ bu, float* __restrict__ hs)
{
    int w = blockIdx.x * (blockDim.x >> 5) + (threadIdx.x >> 5);   // 0..127
    int lane = threadIdx.x & 31;
    int b = w >> 3, s = w & 7;

    float A = -fminf(fmaxf(expf(A_log[s]), 1e-8f), 10.f);
    float Abar = expf(A * (1.f/2048.f));
    float p64  = expf(A * (1.f/32.f));     // Abar^64

    const float* bup = bu + (size_t)(b*NTOK)*NSTATE + s;
    float* hsp = hs + (size_t)(b*NTOK)*NSTATE + s;
    int base = lane * 64;

    // local chunk evaluated from h=0
    float loc = 0.f;
    for (int i = 0; i < 64; i++) loc = Abar*loc + bup[(base + i)*NSTATE];

    // inclusive Kogge-Stone scan over (a, b): x∘y => (ax*ay, ay*bx + by)
    float aa = p64, bb = loc;
    #pragma unroll
    for (int off = 1; off < 32; off <<= 1) {
        float pa = __shfl_up_sync(0xffffffffu, aa, off);
        float pb = __shfl_up_sync(0xffffffffu, bb, off);
        if (lane >= off) { bb = aa*pb + bb; aa = aa*pa; }
    }
    float hin = __shfl_up_sync(0xffffffffu, bb, 1);
    if (lane == 0) hin = 0.f;

    float h = hin;
    for (int i = 0; i < 64; i++) {
        h = Abar*h + bup[(base + i)*NSTATE];
        hsp[(base + i)*NSTATE] = h;
    }
}

// ---------------- ssm output + gated residual ----------------
__global__ void ssm_out_kernel(const float* __restrict__ Cw, const float* __restrict__ Dp,
                               const float* __restrict__ xn, const float* __restrict__ hs,
                               const float* __restrict__ gate, float* __restrict__ seq)
{
    int token = blockIdx.x;
    int tid = threadIdx.x;
    __shared__ float hsl[NSTATE];
    if (tid < NSTATE) hsl[tid] = hs[token*NSTATE + tid];
    __syncthreads();
    float xv = xn[token*DM + tid];
    float o = Dp[tid] * xv;
    #pragma unroll
    for (int s = 0; s < NSTATE; s++) o += hsl[s] * Cw[tid*NSTATE + s];
    int idx = token*DM + tid;
    seq[idx] += gate[idx] * o;
}

// ---------------- generic TN GEMM: C[M,256] = mapA(A)[M,256] @ W[256,256]^T --
// act: 0=none, 1=sigmoid, 2=relu
__global__ void gemm_tn(const float* __restrict__ A, const float* __restrict__ W,
                        const float* __restrict__ bias, float* __restrict__ C,
                        int M, int rpb, int tstride, int rowoff, int act)
{
    const int K = 256, N = 256;
    __shared__ float As[16][68];
    __shared__ float Bs[16][68];
    int m0 = blockIdx.y * 64, n0 = blockIdx.x * 64;
    int tid = threadIdx.x;
    int tx = tid & 15, ty = tid >> 4;
    float acc[4][4] = {};

    for (int k0 = 0; k0 < K; k0 += 16) {
        #pragma unroll
        for (int i = 0; i < 4; i++) {
            int idx = tid + i*256;
            int r = idx >> 4, kk = idx & 15;
            int m = m0 + r;
            int tok = (m / rpb) * tstride + rowoff + (m % rpb);
            As[kk][r] = A[(size_t)tok*K + k0 + kk];
            Bs[kk][r] = W[(size_t)(n0 + r)*K + k0 + kk];
        }
        __syncthreads();
        #pragma unroll
        for (int kk = 0; kk < 16; kk++) {
            float a[4], bv[4];
            #pragma unroll
            for (int i = 0; i < 4; i++) a[i]  = As[kk][ty*4 + i];
            #pragma unroll
            for (int j = 0; j < 4; j++) bv[j] = Bs[kk][tx*4 + j];
            #pragma unroll
            for (int i = 0; i < 4; i++)
                #pragma unroll
                for (int j = 0; j < 4; j++)
                    acc[i][j] += a[i] * bv[j];
        }
        __syncthreads();
    }
    #pragma unroll
    for (int i = 0; i < 4; i++) {
        int m = m0 + ty*4 + i;
        #pragma unroll
        for (int j = 0; j < 4; j++) {
            int n = n0 + tx*4 + j;
            float v = acc[i][j] + bias[n];
            if (act == 1) v = 1.f / (1.f + expf(-v));
            else if (act == 2) v = fmaxf(v, 0.f);
            C[(size_t)m*N + n] = v;
        }
    }
}

// ---------------- flash attention: 64-query tiles, hd=64 ----------------
#define ATT_SMEM (4*64*65*4 + 3*64*4)
__global__ void attn_kernel(const float* __restrict__ Q, const float* __restrict__ Km,
                            const float* __restrict__ V, float* __restrict__ O)
{
    extern __shared__ float sm[];
    float* Qs = sm;                 // 64 x 65
    float* Ks = Qs + 64*65;
    float* Vs = Ks + 64*65;
    float* Ss = Vs + 64*65;
    float* mrow = Ss + 64*65;       // 64
    float* lrow = mrow + 64;
    float* crow = lrow + 64;

    int qb = blockIdx.x, h = blockIdx.y, b = blockIdx.z;
    int tid = threadIdx.x;
    int q0 = qb * 64;

    for (int i = tid; i < 64*64; i += 256) {
        int q = i >> 6, d = i & 63;
        Qs[q*65 + d] = Q[((size_t)(b*NSEQ + q0 + q))*DM + h*64 + d];
    }
    if (tid < 64) { mrow[tid] = -1e30f; lrow[tid] = 0.f; }

    int ty = tid >> 4, tx = tid & 15;
    int qr = ty*4, jc = tx*4;
    float o[4][4] = {};

    for (int kt = 0; kt < 16; kt++) {
        __syncthreads();
        for (int i = tid; i < 64*64; i += 256) {
            int r = i >> 6, d = i & 63;
            size_t g = ((size_t)(b*NSEQ + kt*64 + r))*DM + h*64 + d;
            Ks[r*65 + d] = Km[g];
            Vs[r*65 + d] = V[g];
        }
        __syncthreads();

        // S = Q K^T * scale
        {
            float acc[4][4] = {};
            for (int d = 0; d < 64; d++) {
                float a[4], bv[4];
                #pragma unroll
                for (int i = 0; i < 4; i++) a[i]  = Qs[(qr+i)*65 + d];
                #pragma unroll
                for (int j = 0; j < 4; j++) bv[j] = Ks[(jc+j)*65 + d];
                #pragma unroll
                for (int i = 0; i < 4; i++)
                    #pragma unroll
                    for (int j = 0; j < 4; j++) acc[i][j] += a[i]*bv[j];
            }
            #pragma unroll
            for (int i = 0; i < 4; i++)
                #pragma unroll
                for (int j = 0; j < 4; j++)
                    Ss[(qr+i)*65 + jc + j] = acc[i][j] * 0.125f;
        }
        __syncthreads();

        // online softmax per row
        if (tid < 64) {
            int q = tid;
            float mold = mrow[q], mn = mold;
            for (int j = 0; j < 64; j++) mn = fmaxf(mn, Ss[q*65 + j]);
            float corr = expf(mold - mn);
            float ssum = 0.f;
            for (int j = 0; j < 64; j++) {
                float p = expf(Ss[q*65 + j] - mn);
                Ss[q*65 + j] = p;
                ssum += p;
            }
            lrow[q] = lrow[q]*corr + ssum;
            mrow[q] = mn;
            crow[q] = corr;
        }
        __syncthreads();

        // O = O*corr + P V
        {
            float c[4];
            #pragma unroll
            for (int i = 0; i < 4; i++) c[i] = crow[qr + i];
            float acc[4][4] = {};
            for (int j = 0; j < 64; j++) {
                float p[4], v[4];
                #pragma unroll
                for (int i = 0; i < 4; i++) p[i] = Ss[(qr+i)*65 + j];
                #pragma unroll
                for (int d = 0; d < 4; d++) v[d] = Vs[j*65 + jc + d];
                #pragma unroll
                for (int i = 0; i < 4; i++)
                    #pragma unroll
                    for (int d = 0; d < 4; d++) acc[i][d] += p[i]*v[d];
            }
            #pragma unroll
            for (int i = 0; i < 4; i++)
                #pragma unroll
                for (int d = 0; d < 4; d++) o[i][d] = o[i][d]*c[i] + acc[i][d];
        }
    }

    #pragma unroll
    for (int i = 0; i < 4; i++) {
        float inv = 1.f / lrow[qr + i];
        #pragma unroll
        for (int d = 0; d < 4; d++)
            O[((size_t)(b*NSEQ + q0 + qr + i))*DM + h*64 + jc + d] = o[i][d] * inv;
    }
}

// ---------------- final scalar head ----------------
__global__ void final_kernel(const float* __restrict__ hbuf,
                             const float* __restrict__ w2, const float* __restrict__ b2,
                             float* __restrict__ out)
{
    int warp = threadIdx.x >> 5, lane = threadIdx.x & 31;
    int token = blockIdx.x * 8 + warp;
    const float* hr = hbuf + (size_t)token*DM;
    float s = 0.f;
    #pragma unroll
    for (int i = 0; i < 8; i++) {
        int d = lane + i*32;
        s += hr[d] * w2[d];
    }
    #pragma unroll
    for (int off = 16; off; off >>= 1) s += __shfl_down_sync(0xffffffffu, s, off);
    if (lane == 0) out[token] = s + b2[0];
}

// ---------------- host launch ----------------
extern "C" void kernel_launch(void* const* d_in, const int* in_sizes, int n_in,
                              void* d_out, int out_size)
{
    const float* sparse_coords = (const float*)d_in[0];
    const float* sparse_values = (const float*)d_in[1];
    const float* query_coords  = (const float*)d_in[2];
    const float* t_in          = (const float*)d_in[3];
    const float* noise         = (const float*)d_in[4];
    const float* B_f           = (const float*)d_in[5];
    const float* Wq_in         = (const float*)d_in[6];
    const float* bq_in         = (const float*)d_in[7];
    const float* Wi_in         = (const float*)d_in[8];
    const float* bi_in         = (const float*)d_in[9];
    const float* A_log         = (const float*)d_in[10];
    const float* Bw            = (const float*)d_in[11];
    const float* Cw            = (const float*)d_in[12];
    const float* Dp            = (const float*)d_in[13];
    const float* ln_g          = (const float*)d_in[14];
    const float* ln_b          = (const float*)d_in[15];
    const float* gate_w        = (const float*)d_in[16];
    const float* gate_b        = (const float*)d_in[17];
    const float* in_proj_w     = (const float*)d_in[18];
    const float* in_proj_b     = (const float*)d_in[19];
    const float* out_w         = (const float*)d_in[20];
    const float* out_b         = (const float*)d_in[21];
    const float* dec_w1        = (const float*)d_in[22];
    const float* dec_b1        = (const float*)d_in[23];
    const float* dec_w2        = (const float*)d_in[24];
    const float* dec_b2        = (const float*)d_in[25];
    float* out = (float*)d_out;

    float *p_seq, *p_xn, *p_gate, *p_bu, *p_hs, *p_q, *p_k, *p_v, *p_att, *p_x1, *p_h;
    cudaGetSymbolAddress((void**)&p_seq, g_seq);
    cudaGetSymbolAddress((void**)&p_xn,  g_xn);
    cudaGetSymbolAddress((void**)&p_gate,g_gate);
    cudaGetSymbolAddress((void**)&p_bu,  g_bu);
    cudaGetSymbolAddress((void**)&p_hs,  g_hs);
    cudaGetSymbolAddress((void**)&p_q,   g_q);
    cudaGetSymbolAddress((void**)&p_k,   g_k);
    cudaGetSymbolAddress((void**)&p_v,   g_v);
    cudaGetSymbolAddress((void**)&p_att, g_att);
    cudaGetSymbolAddress((void**)&p_x1,  g_x1);
    cudaGetSymbolAddress((void**)&p_h,   g_h);

    cudaFuncSetAttribute(attn_kernel, cudaFuncAttributeMaxDynamicSharedMemorySize, ATT_SMEM);

    int ntok_all = BATCH*NTOK;          // 32768
    int nq_all   = BATCH*NSEQ;          // 16384

    embed_kernel<<<ntok_all, 256>>>(sparse_coords, sparse_values, query_coords, t_in,
                                    noise, B_f, Wq_in, bq_in, Wi_in, bi_in, p_seq);

    for (int l = 0; l < NLAYER; l++) {
        ln_bu_kernel<<<ntok_all, 256>>>(ln_g + l*DM, ln_b + l*DM, Bw + l*NSTATE*DM,
                                        p_seq, p_xn, p_bu);
        gemm_tn<<<dim3(4, ntok_all/64), 256>>>(p_xn, gate_w + l*DM*DM, gate_b + l*DM,
                                               p_gate, ntok_all, ntok_all, 0, 0, 1);
        scan_kernel<<<16, 256>>>(A_log + l*NSTATE, p_bu, p_hs);
        ssm_out_kernel<<<ntok_all, 256>>>(Cw + l*DM*NSTATE, Dp + l*DM,
                                          p_xn, p_hs, p_gate, p_seq);
    }

    // q from second half of each batch's tokens, k/v from first half
    gemm_tn<<<dim3(4, nq_all/64), 256>>>(p_seq, in_proj_w,            in_proj_b,
                                         p_q, nq_all, NSEQ, NTOK, NSEQ, 0);
    gemm_tn<<<dim3(4, nq_all/64), 256>>>(p_seq, in_proj_w + DM*DM,    in_proj_b + DM,
                                         p_k, nq_all, NSEQ, NTOK, 0, 0);
    gemm_tn<<<dim3(4, nq_all/64), 256>>>(p_seq, in_proj_w + 2*DM*DM,  in_proj_b + 2*DM,
                                         p_v, nq_all, NSEQ, NTOK, 0, 0);

    attn_kernel<<<dim3(16, 4, BATCH), 256, ATT_SMEM>>>(p_q, p_k, p_v, p_att);

    gemm_tn<<<dim3(4, nq_all/64), 256>>>(p_att, out_w,  out_b,  p_x1, nq_all, nq_all, 0, 0, 0);
    gemm_tn<<<dim3(4, nq_all/64), 256>>>(p_x1,  dec_w1, dec_b1, p_h,  nq_all, nq_all, 0, 0, 2);

    final_kernel<<<nq_all/8, 256>>>(p_h, dec_w2, dec_b2, out);
}

// round 2
// speedup vs baseline: 1.2522x; 1.2522x over previous
#include <cuda_runtime.h>

#define BATCH 16
#define NSEQ  1024
#define NTOK  2048
#define DM    256
#define NLAYER 4
#define NSTATE 8
#define NF    16
#define CIN   33
#define LN_EPS 1e-5f

// ---------------- scratch ----------------
__device__ float g_seq [BATCH*NTOK*DM];
__device__ float g_xn  [BATCH*NTOK*DM];
__device__ float g_gate[BATCH*NTOK*DM];
__device__ float g_bu  [BATCH*NSTATE*NTOK];   // [b][s][n] contiguous
__device__ float g_hs  [BATCH*NSTATE*NTOK];
__device__ float g_q   [BATCH*NSEQ*DM];
__device__ float g_k   [BATCH*NSEQ*DM];
__device__ float g_v   [BATCH*NSEQ*DM];
__device__ float g_att [BATCH*NSEQ*DM];
__device__ float g_x1  [BATCH*NSEQ*DM];
__device__ float g_h   [BATCH*NSEQ*DM];

// ---------------- embed ----------------
__global__ void embed_kernel(const float* __restrict__ sparse_coords,
                             const float* __restrict__ sparse_values,
                             const float* __restrict__ query_coords,
                             const float* __restrict__ t_in,
                             const float* __restrict__ noise,
                             const float* __restrict__ B_f,
                             const float* __restrict__ Wq, const float* __restrict__ bq,
                             const float* __restrict__ Wi, const float* __restrict__ bi,
                             float* __restrict__ seq)
{
    int token = blockIdx.x;
    int b = token / NTOK;
    int n = token % NTOK;
    int tid = threadIdx.x;

    __shared__ float feat[CIN];
    const float* W; const float* bias;
    float cx, cy, val;
    if (n < NSEQ) {
        cx = sparse_coords[(b*NSEQ + n)*2 + 0];
        cy = sparse_coords[(b*NSEQ + n)*2 + 1];
        val = sparse_values[b*NSEQ + n];
        W = Wi; bias = bi;
    } else {
        int m = n - NSEQ;
        cx = query_coords[(b*NSEQ + m)*2 + 0];
        cy = query_coords[(b*NSEQ + m)*2 + 1];
        val = noise[b*NSEQ + m];
        W = Wq; bias = bq;
    }
    if (tid < NF) {
        float proj = cx * B_f[tid] + cy * B_f[NF + tid];
        feat[tid]      = sinf(proj);
        feat[NF + tid] = cosf(proj);
    }
    if (tid == 0) feat[2*NF] = val;
    __syncthreads();

    int d = tid;
    float acc = bias[d];
    const float* wrow = W + d*CIN;
    #pragma unroll
    for (int k = 0; k < CIN; k++) acc += feat[k] * wrow[k];

    float tv = t_in[b];
    float e;
    if (d < 128) e = sinf(tv * expf((float)d * (-9.210340371976184f / 127.f)));
    else         e = cosf(tv * expf((float)(d-128) * (-9.210340371976184f / 127.f)));

    seq[token*DM + d] = acc + e;
}

// ---------------- LN + Bu (warp reductions; bu in [b][s][n] layout) ------
__global__ void ln_bu_kernel(const float* __restrict__ lng, const float* __restrict__ lnb,
                             const float* __restrict__ Bw,
                             const float* __restrict__ seq,
                             float* __restrict__ xn_out, float* __restrict__ bu_out)
{
    int token = blockIdx.x;
    int tid = threadIdx.x;
    int w = tid >> 5, lane = tid & 31;
    __shared__ float xs[DM];
    __shared__ float part[16];

    float x = seq[token*DM + tid];
    float s = x;
    #pragma unroll
    for (int o = 16; o; o >>= 1) s += __shfl_xor_sync(0xffffffffu, s, o);
    if (lane == 0) part[w] = s;
    __syncthreads();
    float mu = 0.f;
    #pragma unroll
    for (int i = 0; i < 8; i++) mu += part[i];
    mu *= (1.f/256.f);
    float dx = x - mu;
    float s2 = dx*dx;
    #pragma unroll
    for (int o = 16; o; o >>= 1) s2 += __shfl_xor_sync(0xffffffffu, s2, o);
    __syncthreads();
    if (lane == 0) part[8 + w] = s2;
    __syncthreads();
    float var = 0.f;
    #pragma unroll
    for (int i = 0; i < 8; i++) var += part[8 + i];
    var *= (1.f/256.f);

    float xn = dx * rsqrtf(var + LN_EPS) * lng[tid] + lnb[tid];
    xn_out[token*DM + tid] = xn;
    xs[tid] = xn;
    __syncthreads();

    float bs = 0.f;
    #pragma unroll
    for (int i = 0; i < 8; i++) {
        int d = lane + i*32;
        bs += xs[d] * Bw[w*DM + d];
    }
    #pragma unroll
    for (int o = 16; o; o >>= 1) bs += __shfl_xor_sync(0xffffffffu, bs, o);
    if (lane == 0) {
        int b = token >> 11, n = token & 2047;
        bu_out[((size_t)(b*NSTATE + w))*NTOK + n] = bs;
    }
}

// ---------------- scan: 1 block per (b,s), 32 threads, smem staged -------
__global__ void scan_kernel(const float* __restrict__ A_log,
                            const float* __restrict__ bu, float* __restrict__ hs)
{
    __shared__ float sb[NTOK];
    int wi = blockIdx.x;            // 0..127
    int lane = threadIdx.x;
    int s = wi & 7;

    float A = -fminf(fmaxf(expf(A_log[s]), 1e-8f), 10.f);
    float Abar = expf(A * (1.f/2048.f));
    float p64  = expf(A * (1.f/32.f));

    const float* bup = bu + (size_t)wi*NTOK;
    float* hsp = hs + (size_t)wi*NTOK;

    #pragma unroll
    for (int i = 0; i < 64; i++) sb[lane + i*32] = bup[lane + i*32];
    __syncwarp();

    int base = lane * 64;
    float loc = 0.f;
    #pragma unroll 8
    for (int i = 0; i < 64; i++) loc = Abar*loc + sb[base + i];

    float aa = p64, bb = loc;
    #pragma unroll
    for (int off = 1; off < 32; off <<= 1) {
        float pa = __shfl_up_sync(0xffffffffu, aa, off);
        float pb = __shfl_up_sync(0xffffffffu, bb, off);
        if (lane >= off) { bb = aa*pb + bb; aa = aa*pa; }
    }
    float hin = __shfl_up_sync(0xffffffffu, bb, 1);
    if (lane == 0) hin = 0.f;

    float h = hin;
    #pragma unroll 8
    for (int i = 0; i < 64; i++) {
        h = Abar*h + sb[base + i];
        sb[base + i] = h;
    }
    __syncwarp();
    #pragma unroll
    for (int i = 0; i < 64; i++) hsp[lane + i*32] = sb[lane + i*32];
}

// ---------------- ssm out + gated residual ----------------
__global__ void ssm_out_kernel(const float* __restrict__ Cw, const float* __restrict__ Dp,
                               const float* __restrict__ xn, const float* __restrict__ hs,
                               const float* __restrict__ gate, float* __restrict__ seq)
{
    int token = blockIdx.x;
    int tid = threadIdx.x;
    __shared__ float hsl[NSTATE];
    if (tid < NSTATE) {
        int b = token >> 11, n = token & 2047;
        hsl[tid] = hs[((size_t)(b*NSTATE + tid))*NTOK + n];
    }
    __syncthreads();
    float xv = xn[token*DM + tid];
    float o = Dp[tid] * xv;
    #pragma unroll
    for (int s = 0; s < NSTATE; s++) o += hsl[s] * Cw[tid*NSTATE + s];
    int idx = token*DM + tid;
    seq[idx] += gate[idx] * o;
}

// ---------------- SGEMM: C[M,256] = mapA(A) @ W^T + bias, 128x128x8 ------
// act: 0=none, 1=sigmoid, 2=relu
__global__ __launch_bounds__(256, 2)
void gemm128(const float* __restrict__ A, const float* __restrict__ W,
             const float* __restrict__ bias, float* __restrict__ C,
             int rpb, int tstride, int rowoff, int act)
{
    __shared__ float As[2][8][132];
    __shared__ float Bs[2][8][132];

    int tid = threadIdx.x;
    int m0 = blockIdx.y * 128, n0 = blockIdx.x * 128;

    int arow = tid >> 1;
    int acol = (tid & 1) * 4;

    int m = m0 + arow;
    int tok = (m / rpb) * tstride + rowoff + (m % rpb);
    const float* Aptr = A + (size_t)tok*DM + acol;
    const float* Bptr = W + (size_t)(n0 + arow)*DM + acol;

    int tx = tid & 15, ty = tid >> 4;
    int tx8 = tx * 8, ty8 = ty * 8;

    float acc[8][8] = {};

    // first tile
    float4 av = *(const float4*)Aptr;
    float4 bv = *(const float4*)Bptr;
    As[0][acol+0][arow] = av.x; As[0][acol+1][arow] = av.y;
    As[0][acol+2][arow] = av.z; As[0][acol+3][arow] = av.w;
    Bs[0][acol+0][arow] = bv.x; Bs[0][acol+1][arow] = bv.y;
    Bs[0][acol+2][arow] = bv.z; Bs[0][acol+3][arow] = bv.w;
    __syncthreads();

    #pragma unroll 1
    for (int kt = 0; kt < 32; kt++) {
        int buf = kt & 1;
        float4 av2, bv2;
        if (kt < 31) {
            av2 = *(const float4*)(Aptr + (kt+1)*8);
            bv2 = *(const float4*)(Bptr + (kt+1)*8);
        }
        #pragma unroll
        for (int kk = 0; kk < 8; kk++) {
            float4 a0 = *(const float4*)&As[buf][kk][ty8];
            float4 a1 = *(const float4*)&As[buf][kk][ty8+4];
            float4 b0 = *(const float4*)&Bs[buf][kk][tx8];
            float4 b1 = *(const float4*)&Bs[buf][kk][tx8+4];
            float a[8] = {a0.x,a0.y,a0.z,a0.w,a1.x,a1.y,a1.z,a1.w};
            float bb[8] = {b0.x,b0.y,b0.z,b0.w,b1.x,b1.y,b1.z,b1.w};
            #pragma unroll
            for (int i = 0; i < 8; i++)
                #pragma unroll
                for (int j = 0; j < 8; j++)
                    acc[i][j] += a[i] * bb[j];
        }
        if (kt < 31) {
            int nb = buf ^ 1;
            As[nb][acol+0][arow] = av2.x; As[nb][acol+1][arow] = av2.y;
            As[nb][acol+2][arow] = av2.z; As[nb][acol+3][arow] = av2.w;
            Bs[nb][acol+0][arow] = bv2.x; Bs[nb][acol+1][arow] = bv2.y;
            Bs[nb][acol+2][arow] = bv2.z; Bs[nb][acol+3][arow] = bv2.w;
            __syncthreads();
        }
    }

    float bsv[8];
    #pragma unroll
    for (int j = 0; j < 8; j++) bsv[j] = bias[n0 + tx8 + j];

    #pragma unroll
    for (int i = 0; i < 8; i++) {
        int mm = m0 + ty8 + i;
        float r[8];
        #pragma unroll
        for (int j = 0; j < 8; j++) {
            float v = acc[i][j] + bsv[j];
            if (act == 1) v = 1.f / (1.f + expf(-v));
            else if (act == 2) v = fmaxf(v, 0.f);
            r[j] = v;
        }
        float4 r0 = {r[0],r[1],r[2],r[3]};
        float4 r1 = {r[4],r[5],r[6],r[7]};
        *(float4*)&C[(size_t)mm*DM + n0 + tx8]     = r0;
        *(float4*)&C[(size_t)mm*DM + n0 + tx8 + 4] = r1;
    }
}

// ---------------- flash attention: 128-query tiles, hd=64 ----------------
#define QT_STRIDE 132
#define KT_STRIDE 68
#define ATT2_FLOATS (64*QT_STRIDE + 64*KT_STRIDE + 64*KT_STRIDE + 64*QT_STRIDE + 3*128)
#define ATT2_SMEM   (ATT2_FLOATS*4)

__global__ __launch_bounds__(256, 2)
void attn_kernel(const float* __restrict__ Q, const float* __restrict__ Km,
                 const float* __restrict__ V, float* __restrict__ O)
{
    extern __shared__ float sm[];
    float* Qt = sm;                         // [d][q] 64 x 132
    float* Kt = Qt + 64*QT_STRIDE;          // [d][k] 64 x 68
    float* Vs = Kt + 64*KT_STRIDE;          // [k][d] 64 x 68
    float* St = Vs + 64*KT_STRIDE;          // [k][q] 64 x 132
    float* mrow = St + 64*QT_STRIDE;        // 128
    float* lrow = mrow + 128;
    float* crow = lrow + 128;

    int qb = blockIdx.x, h = blockIdx.y, b = blockIdx.z;
    int tid = threadIdx.x;
    int q0 = qb * 128;

    // load Q tile transposed
    for (int i = tid; i < 128*64; i += 256) {
        int q = i >> 6, d = i & 63;
        Qt[d*QT_STRIDE + q] = Q[((size_t)(b*NSEQ + q0 + q))*DM + h*64 + d];
    }
    if (tid < 128) { mrow[tid] = -1e30f; lrow[tid] = 0.f; }

    int kgrp = tid >> 5;            // 0..7 -> kr
    int kr = kgrp * 8;
    int qc = (tid & 31) * 4;

    int ty = tid >> 4, tx = tid & 15;
    int qr = ty * 8, dc = tx * 4;

    float o[8][4] = {};

    for (int kt = 0; kt < 16; kt++) {
        __syncthreads();
        for (int i = tid; i < 64*64; i += 256) {
            int k = i >> 6, d = i & 63;
            size_t g = ((size_t)(b*NSEQ + kt*64 + k))*DM + h*64 + d;
            Kt[d*KT_STRIDE + k] = Km[g];
            Vs[k*KT_STRIDE + d] = V[g];
        }
        __syncthreads();

        // S^T[k][q] = (K Q^T) * scale : 8k x 4q per thread
        {
            float acc[8][4] = {};
            #pragma unroll 4
            for (int d = 0; d < 64; d++) {
                float4 a0 = *(const float4*)&Kt[d*KT_STRIDE + kr];
                float4 a1 = *(const float4*)&Kt[d*KT_STRIDE + kr + 4];
                float4 bq4 = *(const float4*)&Qt[d*QT_STRIDE + qc];
                float a[8] = {a0.x,a0.y,a0.z,a0.w,a1.x,a1.y,a1.z,a1.w};
                float bb[4] = {bq4.x,bq4.y,bq4.z,bq4.w};
                #pragma unroll
                for (int i = 0; i < 8; i++)
                    #pragma unroll
                    for (int j = 0; j < 4; j++)
                        acc[i][j] += a[i] * bb[j];
            }
            #pragma unroll
            for (int i = 0; i < 8; i++) {
                float4 r = {acc[i][0]*0.125f, acc[i][1]*0.125f,
                            acc[i][2]*0.125f, acc[i][3]*0.125f};
                *(float4*)&St[(kr+i)*QT_STRIDE + qc] = r;
            }
        }
        __syncthreads();

        // online softmax: 2 threads per query
        {
            int q = tid >> 1, hf = tid & 1;
            float mold = mrow[q];
            float mx = mold;
            int j0 = hf * 32;
            #pragma unroll 8
            for (int j = 0; j < 32; j++)
                mx = fmaxf(mx, St[(j0+j)*QT_STRIDE + q]);
            mx = fmaxf(mx, __shfl_xor_sync(0xffffffffu, mx, 1));
            float ssum = 0.f;
            #pragma unroll 8
            for (int j = 0; j < 32; j++) {
                float p = expf(St[(j0+j)*QT_STRIDE + q] - mx);
                St[(j0+j)*QT_STRIDE + q] = p;
                ssum += p;
            }
            ssum += __shfl_xor_sync(0xffffffffu, ssum, 1);
            if (hf == 0) {
                float corr = expf(mold - mx);
                lrow[q] = lrow[q]*corr + ssum;
                mrow[q] = mx;
                crow[q] = corr;
            }
        }
        __syncthreads();

        // O = O*corr + P V : 8q x 4d per thread
        {
            float c[8];
            #pragma unroll
            for (int i = 0; i < 8; i++) c[i] = crow[qr + i];
            float pacc[8][4] = {};
            #pragma unroll 4
            for (int j = 0; j < 64; j++) {
                float4 p0 = *(const float4*)&St[j*QT_STRIDE + qr];
                float4 p1 = *(const float4*)&St[j*QT_STRIDE + qr + 4];
                float4 v4 = *(const float4*)&Vs[j*KT_STRIDE + dc];
                float p[8] = {p0.x,p0.y,p0.z,p0.w,p1.x,p1.y,p1.z,p1.w};
                float vv[4] = {v4.x,v4.y,v4.z,v4.w};
                #pragma unroll
                for (int i = 0; i < 8; i++)
                    #pragma unroll
                    for (int d = 0; d < 4; d++)
                        pacc[i][d] += p[i] * vv[d];
            }
            #pragma unroll
            for (int i = 0; i < 8; i++)
                #pragma unroll
                for (int d = 0; d < 4; d++)
                    o[i][d] = o[i][d]*c[i] + pacc[i][d];
        }
    }

    #pragma unroll
    for (int i = 0; i < 8; i++) {
        float inv = 1.f / lrow[qr + i];
        float4 r = {o[i][0]*inv, o[i][1]*inv, o[i][2]*inv, o[i][3]*inv};
        *(float4*)&O[((size_t)(b*NSEQ + q0 + qr + i))*DM + h*64 + dc] = r;
    }
}

// ---------------- final scalar head ----------------
__global__ void final_kernel(const float* __restrict__ hbuf,
                             const float* __restrict__ w2, const float* __restrict__ b2,
                             float* __restrict__ out)
{
    int warp = threadIdx.x >> 5, lane = threadIdx.x & 31;
    int token = blockIdx.x * 8 + warp;
    const float* hr = hbuf + (size_t)token*DM;
    float s = 0.f;
    #pragma unroll
    for (int i = 0; i < 8; i++) {
        int d = lane + i*32;
        s += hr[d] * w2[d];
    }
    #pragma unroll
    for (int off = 16; off; off >>= 1) s += __shfl_down_sync(0xffffffffu, s, off);
    if (lane == 0) out[token] = s + b2[0];
}

// ---------------- host launch ----------------
extern "C" void kernel_launch(void* const* d_in, const int* in_sizes, int n_in,
                              void* d_out, int out_size)
{
    const float* sparse_coords = (const float*)d_in[0];
    const float* sparse_values = (const float*)d_in[1];
    const float* query_coords  = (const float*)d_in[2];
    const float* t_in          = (const float*)d_in[3];
    const float* noise         = (const float*)d_in[4];
    const float* B_f           = (const float*)d_in[5];
    const float* Wq_in         = (const float*)d_in[6];
    const float* bq_in         = (const float*)d_in[7];
    const float* Wi_in         = (const float*)d_in[8];
    const float* bi_in         = (const float*)d_in[9];
    const float* A_log         = (const float*)d_in[10];
    const float* Bw            = (const float*)d_in[11];
    const float* Cw            = (const float*)d_in[12];
    const float* Dp            = (const float*)d_in[13];
    const float* ln_g          = (const float*)d_in[14];
    const float* ln_b          = (const float*)d_in[15];
    const float* gate_w        = (const float*)d_in[16];
    const float* gate_b        = (const float*)d_in[17];
    const float* in_proj_w     = (const float*)d_in[18];
    const float* in_proj_b     = (const float*)d_in[19];
    const float* out_w         = (const float*)d_in[20];
    const float* out_b         = (const float*)d_in[21];
    const float* dec_w1        = (const float*)d_in[22];
    const float* dec_b1        = (const float*)d_in[23];
    const float* dec_w2        = (const float*)d_in[24];
    const float* dec_b2        = (const float*)d_in[25];
    float* out = (float*)d_out;

    float *p_seq, *p_xn, *p_gate, *p_bu, *p_hs, *p_q, *p_k, *p_v, *p_att, *p_x1, *p_h;
    cudaGetSymbolAddress((void**)&p_seq, g_seq);
    cudaGetSymbolAddress((void**)&p_xn,  g_xn);
    cudaGetSymbolAddress((void**)&p_gate,g_gate);
    cudaGetSymbolAddress((void**)&p_bu,  g_bu);
    cudaGetSymbolAddress((void**)&p_hs,  g_hs);
    cudaGetSymbolAddress((void**)&p_q,   g_q);
    cudaGetSymbolAddress((void**)&p_k,   g_k);
    cudaGetSymbolAddress((void**)&p_v,   g_v);
    cudaGetSymbolAddress((void**)&p_att, g_att);
    cudaGetSymbolAddress((void**)&p_x1,  g_x1);
    cudaGetSymbolAddress((void**)&p_h,   g_h);

    cudaFuncSetAttribute(attn_kernel, cudaFuncAttributeMaxDynamicSharedMemorySize, ATT2_SMEM);

    int ntok_all = BATCH*NTOK;          // 32768
    int nq_all   = BATCH*NSEQ;          // 16384
    const int BIGR = 1 << 30;

    embed_kernel<<<ntok_all, 256>>>(sparse_coords, sparse_values, query_coords, t_in,
                                    noise, B_f, Wq_in, bq_in, Wi_in, bi_in, p_seq);

    for (int l = 0; l < NLAYER; l++) {
        ln_bu_kernel<<<ntok_all, 256>>>(ln_g + l*DM, ln_b + l*DM, Bw + l*NSTATE*DM,
                                        p_seq, p_xn, p_bu);
        gemm128<<<dim3(2, ntok_all/128), 256>>>(p_xn, gate_w + l*DM*DM, gate_b + l*DM,
                                                p_gate, BIGR, 0, 0, 1);
        scan_kernel<<<BATCH*NSTATE, 32>>>(A_log + l*NSTATE, p_bu, p_hs);
        ssm_out_kernel<<<ntok_all, 256>>>(Cw + l*DM*NSTATE, Dp + l*DM,
                                          p_xn, p_hs, p_gate, p_seq);
    }

    gemm128<<<dim3(2, nq_all/128), 256>>>(p_seq, in_proj_w,           in_proj_b,
                                          p_q, NSEQ, NTOK, NSEQ, 0);
    gemm128<<<dim3(2, nq_all/128), 256>>>(p_seq, in_proj_w + DM*DM,   in_proj_b + DM,
                                          p_k, NSEQ, NTOK, 0, 0);
    gemm128<<<dim3(2, nq_all/128), 256>>>(p_seq, in_proj_w + 2*DM*DM, in_proj_b + 2*DM,
                                          p_v, NSEQ, NTOK, 0, 0);

    attn_kernel<<<dim3(8, 4, BATCH), 256, ATT2_SMEM>>>(p_q, p_k, p_v, p_att);

    gemm128<<<dim3(2, nq_all/128), 256>>>(p_att, out_w,  out_b,  p_x1, BIGR, 0, 0, 0);
    gemm128<<<dim3(2, nq_all/128), 256>>>(p_x1,  dec_w1, dec_b1, p_h,  BIGR, 0, 0, 2);

    final_kernel<<<nq_all/8, 256>>>(p_h, dec_w2, dec_b2, out);
}

// round 3
// speedup vs baseline: 1.4140x; 1.1292x over previous
#include <cuda_runtime.h>

#define BATCH 16
#define NSEQ  1024
#define NTOK  2048
#define DM    256
#define NLAYER 4
#define NSTATE 8
#define NF    16
#define CIN   33
#define LN_EPS 1e-5f

// ---------------- scratch ----------------
__device__ float g_seq [BATCH*NTOK*DM];
__device__ float g_xn  [BATCH*NTOK*DM];
__device__ float g_gate[BATCH*NTOK*DM];
__device__ float g_bu  [BATCH*NSTATE*NTOK];
__device__ float g_hs  [BATCH*NSTATE*NTOK];
__device__ float g_q   [BATCH*NSEQ*DM];
__device__ float g_k   [BATCH*NSEQ*DM];
__device__ float g_v   [BATCH*NSEQ*DM];
__device__ float g_att [BATCH*NSEQ*DM];
__device__ float g_x1  [BATCH*NSEQ*DM];
__device__ float g_h   [BATCH*NSEQ*DM];

// ---------------- tf32 helpers ----------------
__device__ __forceinline__ unsigned f2tf(float x) {
    unsigned r;
    asm("cvt.rna.tf32.f32 %0, %1;" : "=r"(r) : "f"(x));
    return r;
}
__device__ __forceinline__ void mma8(float (&d)[4], const unsigned* a, const unsigned* b) {
    asm volatile("mma.sync.aligned.m16n8k8.row.col.f32.tf32.tf32.f32 "
        "{%0,%1,%2,%3}, {%4,%5,%6,%7}, {%8,%9}, {%0,%1,%2,%3};"
        : "+f"(d[0]), "+f"(d[1]), "+f"(d[2]), "+f"(d[3])
        : "r"(a[0]), "r"(a[1]), "r"(a[2]), "r"(a[3]), "r"(b[0]), "r"(b[1]));
}

// ---------------- embed ----------------
__global__ void embed_kernel(const float* __restrict__ sparse_coords,
                             const float* __restrict__ sparse_values,
                             const float* __restrict__ query_coords,
                             const float* __restrict__ t_in,
                             const float* __restrict__ noise,
                             const float* __restrict__ B_f,
                             const float* __restrict__ Wq, const float* __restrict__ bq,
                             const float* __restrict__ Wi, const float* __restrict__ bi,
                             float* __restrict__ seq)
{
    int token = blockIdx.x;
    int b = token / NTOK;
    int n = token % NTOK;
    int tid = threadIdx.x;

    __shared__ float feat[CIN];
    const float* W; const float* bias;
    float cx, cy, val;
    if (n < NSEQ) {
        cx = sparse_coords[(b*NSEQ + n)*2 + 0];
        cy = sparse_coords[(b*NSEQ + n)*2 + 1];
        val = sparse_values[b*NSEQ + n];
        W = Wi; bias = bi;
    } else {
        int m = n - NSEQ;
        cx = query_coords[(b*NSEQ + m)*2 + 0];
        cy = query_coords[(b*NSEQ + m)*2 + 1];
        val = noise[b*NSEQ + m];
        W = Wq; bias = bq;
    }
    if (tid < NF) {
        float proj = cx * B_f[tid] + cy * B_f[NF + tid];
        feat[tid]      = sinf(proj);
        feat[NF + tid] = cosf(proj);
    }
    if (tid == 0) feat[2*NF] = val;
    __syncthreads();

    int d = tid;
    float acc = bias[d];
    const float* wrow = W + d*CIN;
    #pragma unroll
    for (int k = 0; k < CIN; k++) acc += feat[k] * wrow[k];

    float tv = t_in[b];
    float e;
    if (d < 128) e = sinf(tv * expf((float)d * (-9.210340371976184f / 127.f)));
    else         e = cosf(tv * expf((float)(d-128) * (-9.210340371976184f / 127.f)));

    seq[token*DM + d] = acc + e;
}

// ---------------- LN + Bu ----------------
__global__ void ln_bu_kernel(const float* __restrict__ lng, const float* __restrict__ lnb,
                             const float* __restrict__ Bw,
                             const float* __restrict__ seq,
                             float* __restrict__ xn_out, float* __restrict__ bu_out)
{
    int token = blockIdx.x;
    int tid = threadIdx.x;
    int w = tid >> 5, lane = tid & 31;
    __shared__ float xs[DM];
    __shared__ float part[16];

    float x = seq[token*DM + tid];
    float s = x;
    #pragma unroll
    for (int o = 16; o; o >>= 1) s += __shfl_xor_sync(0xffffffffu, s, o);
    if (lane == 0) part[w] = s;
    __syncthreads();
    float mu = 0.f;
    #pragma unroll
    for (int i = 0; i < 8; i++) mu += part[i];
    mu *= (1.f/256.f);
    float dx = x - mu;
    float s2 = dx*dx;
    #pragma unroll
    for (int o = 16; o; o >>= 1) s2 += __shfl_xor_sync(0xffffffffu, s2, o);
    __syncthreads();
    if (lane == 0) part[8 + w] = s2;
    __syncthreads();
    float var = 0.f;
    #pragma unroll
    for (int i = 0; i < 8; i++) var += part[8 + i];
    var *= (1.f/256.f);

    float xn = dx * rsqrtf(var + LN_EPS) * lng[tid] + lnb[tid];
    xn_out[token*DM + tid] = xn;
    xs[tid] = xn;
    __syncthreads();

    float bs = 0.f;
    #pragma unroll
    for (int i = 0; i < 8; i++) {
        int d = lane + i*32;
        bs += xs[d] * Bw[w*DM + d];
    }
    #pragma unroll
    for (int o = 16; o; o >>= 1) bs += __shfl_xor_sync(0xffffffffu, bs, o);
    if (lane == 0) {
        int b = token >> 11, n = token & 2047;
        bu_out[((size_t)(b*NSTATE + w))*NTOK + n] = bs;
    }
}

// ---------------- scan ----------------
__global__ void scan_kernel(const float* __restrict__ A_log,
                            const float* __restrict__ bu, float* __restrict__ hs)
{
    __shared__ float sb[NTOK];
    int wi = blockIdx.x;
    int lane = threadIdx.x;
    int s = wi & 7;

    float A = -fminf(fmaxf(expf(A_log[s]), 1e-8f), 10.f);
    float Abar = expf(A * (1.f/2048.f));
    float p64  = expf(A * (1.f/32.f));

    const float* bup = bu + (size_t)wi*NTOK;
    float* hsp = hs + (size_t)wi*NTOK;

    #pragma unroll
    for (int i = 0; i < 64; i++) sb[lane + i*32] = bup[lane + i*32];
    __syncwarp();

    int base = lane * 64;
    float loc = 0.f;
    #pragma unroll 8
    for (int i = 0; i < 64; i++) loc = Abar*loc + sb[base + i];

    float aa = p64, bb = loc;
    #pragma unroll
    for (int off = 1; off < 32; off <<= 1) {
        float pa = __shfl_up_sync(0xffffffffu, aa, off);
        float pb = __shfl_up_sync(0xffffffffu, bb, off);
        if (lane >= off) { bb = aa*pb + bb; aa = aa*pa; }
    }
    float hin = __shfl_up_sync(0xffffffffu, bb, 1);
    if (lane == 0) hin = 0.f;

    float h = hin;
    #pragma unroll 8
    for (int i = 0; i < 64; i++) {
        h = Abar*h + sb[base + i];
        sb[base + i] = h;
    }
    __syncwarp();
    #pragma unroll
    for (int i = 0; i < 64; i++) hsp[lane + i*32] = sb[lane + i*32];
}

// ---------------- ssm out + gated residual ----------------
__global__ void ssm_out_kernel(const float* __restrict__ Cw, const float* __restrict__ Dp,
                               const float* __restrict__ xn, const float* __restrict__ hs,
                               const float* __restrict__ gate, float* __restrict__ seq)
{
    int token = blockIdx.x;
    int tid = threadIdx.x;
    __shared__ float hsl[NSTATE];
    if (tid < NSTATE) {
        int b = token >> 11, n = token & 2047;
        hsl[tid] = hs[((size_t)(b*NSTATE + tid))*NTOK + n];
    }
    __syncthreads();
    float xv = xn[token*DM + tid];
    float o = Dp[tid] * xv;
    #pragma unroll
    for (int s = 0; s < NSTATE; s++) o += hsl[s] * Cw[tid*NSTATE + s];
    int idx = token*DM + tid;
    seq[idx] += gate[idx] * o;
}

// ---------------- tensor-core GEMM (tf32x3): C = mapA(A) @ W^T + bias ----
// block tile 128x128, K chunks of 16, 8 warps of 32(m)x64(n)
#define GSK 20
#define GEMM_SMEM (4*2*128*GSK*4)

__global__ __launch_bounds__(256, 1)
void gemm_tc(const float* __restrict__ A, const float* __restrict__ W,
             const float* __restrict__ bias, float* __restrict__ C,
             int rpb, int tstride, int rowoff, int act)
{
    extern __shared__ unsigned gsm[];
    unsigned* Ah = gsm;                      // [2][128][GSK]
    unsigned* Al = Ah + 2*128*GSK;
    unsigned* Bh = Al + 2*128*GSK;
    unsigned* Bl = Bh + 2*128*GSK;

    int tid = threadIdx.x;
    int m0 = blockIdx.y * 128, n0 = blockIdx.x * 128;

    int r  = tid >> 1;
    int cb = (tid & 1) * 8;
    int m = m0 + r;
    int tok = (m / rpb) * tstride + rowoff + (m % rpb);
    const float* Aptr = A + (size_t)tok*DM + cb;
    const float* Bptr = W + (size_t)(n0 + r)*DM + cb;

    int w = tid >> 5, lane = tid & 31;
    int g = lane >> 2, t = lane & 3;
    int wm = w >> 1, wn = w & 1;             // warp tile m: wm*32, n: wn*64

    float acc[2][8][4] = {};

    // ---- chunk load helper (macro-ish via lambda) ----
    auto store_chunk = [&](int buf, float4 a0, float4 a1, float4 b0, float4 b1) {
        unsigned hi[8], lo[8];
        float f[8] = {a0.x,a0.y,a0.z,a0.w,a1.x,a1.y,a1.z,a1.w};
        #pragma unroll
        for (int i = 0; i < 8; i++) {
            hi[i] = f2tf(f[i]);
            lo[i] = f2tf(f[i] - __uint_as_float(hi[i]));
        }
        unsigned* pa = Ah + (buf*128 + r)*GSK + cb;
        unsigned* pl = Al + (buf*128 + r)*GSK + cb;
        *(uint4*)pa     = make_uint4(hi[0],hi[1],hi[2],hi[3]);
        *(uint4*)(pa+4) = make_uint4(hi[4],hi[5],hi[6],hi[7]);
        *(uint4*)pl     = make_uint4(lo[0],lo[1],lo[2],lo[3]);
        *(uint4*)(pl+4) = make_uint4(lo[4],lo[5],lo[6],lo[7]);
        float fb[8] = {b0.x,b0.y,b0.z,b0.w,b1.x,b1.y,b1.z,b1.w};
        #pragma unroll
        for (int i = 0; i < 8; i++) {
            hi[i] = f2tf(fb[i]);
            lo[i] = f2tf(fb[i] - __uint_as_float(hi[i]));
        }
        unsigned* pb = Bh + (buf*128 + r)*GSK + cb;
        unsigned* pq = Bl + (buf*128 + r)*GSK + cb;
        *(uint4*)pb     = make_uint4(hi[0],hi[1],hi[2],hi[3]);
        *(uint4*)(pb+4) = make_uint4(hi[4],hi[5],hi[6],hi[7]);
        *(uint4*)pq     = make_uint4(lo[0],lo[1],lo[2],lo[3]);
        *(uint4*)(pq+4) = make_uint4(lo[4],lo[5],lo[6],lo[7]);
    };

    // first chunk
    {
        float4 a0 = *(const float4*)Aptr;
        float4 a1 = *(const float4*)(Aptr + 4);
        float4 b0 = *(const float4*)Bptr;
        float4 b1 = *(const float4*)(Bptr + 4);
        store_chunk(0, a0, a1, b0, b1);
    }
    __syncthreads();

    #pragma unroll 1
    for (int ck = 0; ck < 16; ck++) {
        int buf = ck & 1;
        float4 a0, a1, b0, b1;
        if (ck < 15) {
            a0 = *(const float4*)(Aptr + (ck+1)*16);
            a1 = *(const float4*)(Aptr + (ck+1)*16 + 4);
            b0 = *(const float4*)(Bptr + (ck+1)*16);
            b1 = *(const float4*)(Bptr + (ck+1)*16 + 4);
        }
        #pragma unroll
        for (int kk = 0; kk < 16; kk += 8) {
            unsigned ah[2][4], al[2][4], bh[8][2], bl[8][2];
            #pragma unroll
            for (int mt = 0; mt < 2; mt++) {
                int row = wm*32 + mt*16;
                const unsigned* ph = Ah + (buf*128 + row)*GSK + kk + t;
                const unsigned* pl = Al + (buf*128 + row)*GSK + kk + t;
                ah[mt][0] = ph[(g)*GSK];
                ah[mt][1] = ph[(g+8)*GSK];
                ah[mt][2] = ph[(g)*GSK + 4];
                ah[mt][3] = ph[(g+8)*GSK + 4];
                al[mt][0] = pl[(g)*GSK];
                al[mt][1] = pl[(g+8)*GSK];
                al[mt][2] = pl[(g)*GSK + 4];
                al[mt][3] = pl[(g+8)*GSK + 4];
            }
            #pragma unroll
            for (int nt = 0; nt < 8; nt++) {
                int col = wn*64 + nt*8;
                const unsigned* ph = Bh + (buf*128 + col + g)*GSK + kk + t;
                const unsigned* pl = Bl + (buf*128 + col + g)*GSK + kk + t;
                bh[nt][0] = ph[0];
                bh[nt][1] = ph[4];
                bl[nt][0] = pl[0];
                bl[nt][1] = pl[4];
            }
            #pragma unroll
            for (int mt = 0; mt < 2; mt++)
                #pragma unroll
                for (int nt = 0; nt < 8; nt++) {
                    mma8(acc[mt][nt], ah[mt], bh[nt]);
                    mma8(acc[mt][nt], ah[mt], bl[nt]);
                    mma8(acc[mt][nt], al[mt], bh[nt]);
                }
        }
        if (ck < 15) {
            store_chunk(buf ^ 1, a0, a1, b0, b1);
            __syncthreads();
        }
    }

    // epilogue
    #pragma unroll
    for (int mt = 0; mt < 2; mt++) {
        int row0 = m0 + wm*32 + mt*16 + g;
        #pragma unroll
        for (int nt = 0; nt < 8; nt++) {
            int col = n0 + wn*64 + nt*8 + t*2;
            float b0 = bias[col], b1 = bias[col+1];
            float v0 = acc[mt][nt][0] + b0;
            float v1 = acc[mt][nt][1] + b1;
            float v2 = acc[mt][nt][2] + b0;
            float v3 = acc[mt][nt][3] + b1;
            if (act == 1) {
                v0 = 1.f/(1.f+__expf(-v0)); v1 = 1.f/(1.f+__expf(-v1));
                v2 = 1.f/(1.f+__expf(-v2)); v3 = 1.f/(1.f+__expf(-v3));
            } else if (act == 2) {
                v0 = fmaxf(v0,0.f); v1 = fmaxf(v1,0.f);
                v2 = fmaxf(v2,0.f); v3 = fmaxf(v3,0.f);
            }
            *(float2*)&C[(size_t)row0*DM + col]     = make_float2(v0, v1);
            *(float2*)&C[(size_t)(row0+8)*DM + col] = make_float2(v2, v3);
        }
    }
}

// ---------------- flash attention with tf32 mma ----------------
// q-tile 128, k-tile 64, hd 64; 8 warps: 4(q) x 2(k|d)
#define QS_S 68
#define KS_S 68
#define VS_S 72
#define ST_S 68
#define ATT_SMEM ((128*QS_S + 64*KS_S + 64*VS_S + 128*ST_S + 3*128)*4)

__global__ __launch_bounds__(256, 1)
void attn_kernel(const float* __restrict__ Q, const float* __restrict__ Km,
                 const float* __restrict__ V, float* __restrict__ O)
{
    extern __shared__ unsigned asm_[];
    unsigned* Qs = asm_;                 // [128][QS_S] tf32 (pre-scaled)
    unsigned* Ks = Qs + 128*QS_S;        // [64][KS_S]  tf32
    unsigned* Vs = Ks + 64*KS_S;         // [64][VS_S]  tf32  (k-major rows)
    float*    St = (float*)(Vs + 64*VS_S);   // [128][ST_S]
    unsigned* St_u = (unsigned*)St;
    float* mrow = St + 128*ST_S;
    float* lrow = mrow + 128;
    float* crow = lrow + 128;

    int qb = blockIdx.x, h = blockIdx.y, b = blockIdx.z;
    int tid = threadIdx.x;
    int q0 = qb * 128;

    int w = tid >> 5, lane = tid & 31;
    int g = lane >> 2, t = lane & 3;
    int wq = w >> 1, wk = w & 1;

    // load Q tile (scaled by 1/8) as tf32
    for (int i = tid; i < 128*16; i += 256) {
        int q = i >> 4, d4 = (i & 15) * 4;
        float4 v = *(const float4*)&Q[((size_t)(b*NSEQ + q0 + q))*DM + h*64 + d4];
        *(uint4*)&Qs[q*QS_S + d4] = make_uint4(
            f2tf(v.x*0.125f), f2tf(v.y*0.125f), f2tf(v.z*0.125f), f2tf(v.w*0.125f));
    }
    if (tid < 128) { mrow[tid] = -1e30f; lrow[tid] = 0.f; }

    float oacc[2][4][4] = {};

    for (int kt = 0; kt < 16; kt++) {
        __syncthreads();
        for (int i = tid; i < 64*16; i += 256) {
            int k = i >> 4, d4 = (i & 15) * 4;
            size_t gaddr = ((size_t)(b*NSEQ + kt*64 + k))*DM + h*64 + d4;
            float4 kv = *(const float4*)&Km[gaddr];
            float4 vv = *(const float4*)&V[gaddr];
            *(uint4*)&Ks[k*KS_S + d4] = make_uint4(f2tf(kv.x), f2tf(kv.y), f2tf(kv.z), f2tf(kv.w));
            *(uint4*)&Vs[k*VS_S + d4] = make_uint4(f2tf(vv.x), f2tf(vv.y), f2tf(vv.z), f2tf(vv.w));
        }
        __syncthreads();

        // S = Q K^T : warp tile 32q x 32k
        {
            float sacc[2][4][4] = {};
            #pragma unroll
            for (int dk = 0; dk < 64; dk += 8) {
                unsigned qa[2][4], kb[4][2];
                #pragma unroll
                for (int mt = 0; mt < 2; mt++) {
                    const unsigned* p = Qs + (wq*32 + mt*16)*QS_S + dk + t;
                    qa[mt][0] = p[(g)*QS_S];
                    qa[mt][1] = p[(g+8)*QS_S];
                    qa[mt][2] = p[(g)*QS_S + 4];
                    qa[mt][3] = p[(g+8)*QS_S + 4];
                }
                #pragma unroll
                for (int nt = 0; nt < 4; nt++) {
                    const unsigned* p = Ks + (wk*32 + nt*8 + g)*KS_S + dk + t;
                    kb[nt][0] = p[0];
                    kb[nt][1] = p[4];
                }
                #pragma unroll
                for (int mt = 0; mt < 2; mt++)
                    #pragma unroll
                    for (int nt = 0; nt < 4; nt++)
                        mma8(sacc[mt][nt], qa[mt], kb[nt]);
            }
            #pragma unroll
            for (int mt = 0; mt < 2; mt++) {
                int row = wq*32 + mt*16 + g;
                #pragma unroll
                for (int nt = 0; nt < 4; nt++) {
                    int col = wk*32 + nt*8 + t*2;
                    *(float2*)&St[row*ST_S + col]     = make_float2(sacc[mt][nt][0], sacc[mt][nt][1]);
                    *(float2*)&St[(row+8)*ST_S + col] = make_float2(sacc[mt][nt][2], sacc[mt][nt][3]);
                }
            }
        }
        __syncthreads();

        // online softmax: 2 threads per query row; store P as tf32
        {
            int q = tid >> 1, hf = tid & 1;
            float mold = mrow[q];
            float mx = mold;
            int j0 = hf * 32;
            float* row = St + q*ST_S + j0;
            #pragma unroll 8
            for (int j = 0; j < 32; j++) mx = fmaxf(mx, row[j]);
            mx = fmaxf(mx, __shfl_xor_sync(0xffffffffu, mx, 1));
            float ssum = 0.f;
            unsigned* rowu = St_u + q*ST_S + j0;
            #pragma unroll 8
            for (int j = 0; j < 32; j++) {
                float p = __expf(row[j] - mx);
                ssum += p;
                rowu[j] = f2tf(p);
            }
            ssum += __shfl_xor_sync(0xffffffffu, ssum, 1);
            if (hf == 0) {
                float corr = __expf(mold - mx);
                lrow[q] = lrow[q]*corr + ssum;
                mrow[q] = mx;
                crow[q] = corr;
            }
        }
        __syncthreads();

        // O = O*corr + P V : warp tile 32q x 32d
        {
            #pragma unroll
            for (int mt = 0; mt < 2; mt++) {
                float c0 = crow[wq*32 + mt*16 + g];
                float c1 = crow[wq*32 + mt*16 + g + 8];
                #pragma unroll
                for (int nt = 0; nt < 4; nt++) {
                    oacc[mt][nt][0] *= c0; oacc[mt][nt][1] *= c0;
                    oacc[mt][nt][2] *= c1; oacc[mt][nt][3] *= c1;
                }
            }
            #pragma unroll
            for (int kk = 0; kk < 64; kk += 8) {
                unsigned pa[2][4], vb[4][2];
                #pragma unroll
                for (int mt = 0; mt < 2; mt++) {
                    const unsigned* p = St_u + (wq*32 + mt*16)*ST_S + kk + t;
                    pa[mt][0] = p[(g)*ST_S];
                    pa[mt][1] = p[(g+8)*ST_S];
                    pa[mt][2] = p[(g)*ST_S + 4];
                    pa[mt][3] = p[(g+8)*ST_S + 4];
                }
                #pragma unroll
                for (int nt = 0; nt < 4; nt++) {
                    const unsigned* p = Vs + (kk + t)*VS_S + wk*32 + nt*8 + g;
                    vb[nt][0] = p[0];
                    vb[nt][1] = p[4*VS_S];
                }
                #pragma unroll
                for (int mt = 0; mt < 2; mt++)
                    #pragma unroll
                    for (int nt = 0; nt < 4; nt++)
                        mma8(oacc[mt][nt], pa[mt], vb[nt]);
            }
        }
    }

    __syncthreads();
    #pragma unroll
    for (int mt = 0; mt < 2; mt++) {
        int row = wq*32 + mt*16 + g;
        float inv0 = 1.f / lrow[row];
        float inv1 = 1.f / lrow[row + 8];
        #pragma unroll
        for (int nt = 0; nt < 4; nt++) {
            int col = wk*32 + nt*8 + t*2;
            *(float2*)&O[((size_t)(b*NSEQ + q0 + row))*DM + h*64 + col] =
                make_float2(oacc[mt][nt][0]*inv0, oacc[mt][nt][1]*inv0);
            *(float2*)&O[((size_t)(b*NSEQ + q0 + row + 8))*DM + h*64 + col] =
                make_float2(oacc[mt][nt][2]*inv1, oacc[mt][nt][3]*inv1);
        }
    }
}

// ---------------- final scalar head ----------------
__global__ void final_kernel(const float* __restrict__ hbuf,
                             const float* __restrict__ w2, const float* __restrict__ b2,
                             float* __restrict__ out)
{
    int warp = threadIdx.x >> 5, lane = threadIdx.x & 31;
    int token = blockIdx.x * 8 + warp;
    const float* hr = hbuf + (size_t)token*DM;
    float s = 0.f;
    #pragma unroll
    for (int i = 0; i < 8; i++) {
        int d = lane + i*32;
        s += hr[d] * w2[d];
    }
    #pragma unroll
    for (int off = 16; off; off >>= 1) s += __shfl_down_sync(0xffffffffu, s, off);
    if (lane == 0) out[token] = s + b2[0];
}

// ---------------- host launch ----------------
extern "C" void kernel_launch(void* const* d_in, const int* in_sizes, int n_in,
                              void* d_out, int out_size)
{
    const float* sparse_coords = (const float*)d_in[0];
    const float* sparse_values = (const float*)d_in[1];
    const float* query_coords  = (const float*)d_in[2];
    const float* t_in          = (const float*)d_in[3];
    const float* noise         = (const float*)d_in[4];
    const float* B_f           = (const float*)d_in[5];
    const float* Wq_in         = (const float*)d_in[6];
    const float* bq_in         = (const float*)d_in[7];
    const float* Wi_in         = (const float*)d_in[8];
    const float* bi_in         = (const float*)d_in[9];
    const float* A_log         = (const float*)d_in[10];
    const float* Bw            = (const float*)d_in[11];
    const float* Cw            = (const float*)d_in[12];
    const float* Dp            = (const float*)d_in[13];
    const float* ln_g          = (const float*)d_in[14];
    const float* ln_b          = (const float*)d_in[15];
    const float* gate_w        = (const float*)d_in[16];
    const float* gate_b        = (const float*)d_in[17];
    const float* in_proj_w     = (const float*)d_in[18];
    const float* in_proj_b     = (const float*)d_in[19];
    const float* out_w         = (const float*)d_in[20];
    const float* out_b         = (const float*)d_in[21];
    const float* dec_w1        = (const float*)d_in[22];
    const float* dec_b1        = (const float*)d_in[23];
    const float* dec_w2        = (const float*)d_in[24];
    const float* dec_b2        = (const float*)d_in[25];
    float* out = (float*)d_out;

    float *p_seq, *p_xn, *p_gate, *p_bu, *p_hs, *p_q, *p_k, *p_v, *p_att, *p_x1, *p_h;
    cudaGetSymbolAddress((void**)&p_seq, g_seq);
    cudaGetSymbolAddress((void**)&p_xn,  g_xn);
    cudaGetSymbolAddress((void**)&p_gate,g_gate);
    cudaGetSymbolAddress((void**)&p_bu,  g_bu);
    cudaGetSymbolAddress((void**)&p_hs,  g_hs);
    cudaGetSymbolAddress((void**)&p_q,   g_q);
    cudaGetSymbolAddress((void**)&p_k,   g_k);
    cudaGetSymbolAddress((void**)&p_v,   g_v);
    cudaGetSymbolAddress((void**)&p_att, g_att);
    cudaGetSymbolAddress((void**)&p_x1,  g_x1);
    cudaGetSymbolAddress((void**)&p_h,   g_h);

    cudaFuncSetAttribute(gemm_tc, cudaFuncAttributeMaxDynamicSharedMemorySize, GEMM_SMEM);
    cudaFuncSetAttribute(attn_kernel, cudaFuncAttributeMaxDynamicSharedMemorySize, ATT_SMEM);

    int ntok_all = BATCH*NTOK;
    int nq_all   = BATCH*NSEQ;
    const int BIGR = 1 << 30;

    embed_kernel<<<ntok_all, 256>>>(sparse_coords, sparse_values, query_coords, t_in,
                                    noise, B_f, Wq_in, bq_in, Wi_in, bi_in, p_seq);

    for (int l = 0; l < NLAYER; l++) {
        ln_bu_kernel<<<ntok_all, 256>>>(ln_g + l*DM, ln_b + l*DM, Bw + l*NSTATE*DM,
                                        p_seq, p_xn, p_bu);
        gemm_tc<<<dim3(2, ntok_all/128), 256, GEMM_SMEM>>>(p_xn, gate_w + l*DM*DM, gate_b + l*DM,
                                                           p_gate, BIGR, 0, 0, 1);
        scan_kernel<<<BATCH*NSTATE, 32>>>(A_log + l*NSTATE, p_bu, p_hs);
        ssm_out_kernel<<<ntok_all, 256>>>(Cw + l*DM*NSTATE, Dp + l*DM,
                                          p_xn, p_hs, p_gate, p_seq);
    }

    gemm_tc<<<dim3(2, nq_all/128), 256, GEMM_SMEM>>>(p_seq, in_proj_w,           in_proj_b,
                                                     p_q, NSEQ, NTOK, NSEQ, 0);
    gemm_tc<<<dim3(2, nq_all/128), 256, GEMM_SMEM>>>(p_seq, in_proj_w + DM*DM,   in_proj_b + DM,
                                                     p_k, NSEQ, NTOK, 0, 0);
    gemm_tc<<<dim3(2, nq_all/128), 256, GEMM_SMEM>>>(p_seq, in_proj_w + 2*DM*DM, in_proj_b + 2*DM,
                                                     p_v, NSEQ, NTOK, 0, 0);

    attn_kernel<<<dim3(8, 4, BATCH), 256, ATT_SMEM>>>(p_q, p_k, p_v, p_att);

    gemm_tc<<<dim3(2, nq_all/128), 256, GEMM_SMEM>>>(p_att, out_w,  out_b,  p_x1, BIGR, 0, 0, 0);
    gemm_tc<<<dim3(2, nq_all/128), 256, GEMM_SMEM>>>(p_x1,  dec_w1, dec_b1, p_h,  BIGR, 0, 0, 2);

    final_kernel<<<nq_all/8, 256>>>(p_h, dec_w2, dec_b2, out);
}

// round 4
// speedup vs baseline: 1.4692x; 1.0390x over previous
#include <cuda_runtime.h>

#define BATCH 16
#define NSEQ  1024
#define NTOK  2048
#define DM    256
#define NLAYER 4
#define NSTATE 8
#define NF    16
#define CIN   33
#define LN_EPS 1e-5f

// ---------------- scratch ----------------
__device__ float g_seq [BATCH*NTOK*DM];
__device__ float g_xn  [BATCH*NTOK*DM];
__device__ float g_gate[BATCH*NTOK*DM];
__device__ float g_bu  [BATCH*NSTATE*NTOK];
__device__ float g_hs  [BATCH*NSTATE*NTOK];
__device__ float g_q   [BATCH*NSEQ*DM];
__device__ float g_k   [BATCH*NSEQ*DM];
__device__ float g_v   [BATCH*NSEQ*DM];
__device__ float g_att [BATCH*NSEQ*DM];
__device__ float g_x1  [BATCH*NSEQ*DM];

// ---------------- helpers ----------------
__device__ __forceinline__ unsigned f2tf(float x) {
    unsigned r;
    asm("cvt.rna.tf32.f32 %0, %1;" : "=r"(r) : "f"(x));
    return r;
}
__device__ __forceinline__ void mma8(float (&d)[4], const unsigned* a, const unsigned* b) {
    asm volatile("mma.sync.aligned.m16n8k8.row.col.f32.tf32.tf32.f32 "
        "{%0,%1,%2,%3}, {%4,%5,%6,%7}, {%8,%9}, {%0,%1,%2,%3};"
        : "+f"(d[0]), "+f"(d[1]), "+f"(d[2]), "+f"(d[3])
        : "r"(a[0]), "r"(a[1]), "r"(a[2]), "r"(a[3]), "r"(b[0]), "r"(b[1]));
}
__device__ __forceinline__ void cpa16(unsigned s, const void* g) {
    asm volatile("cp.async.cg.shared.global [%0], [%1], 16;" :: "r"(s), "l"(g));
}
#define CP_COMMIT() asm volatile("cp.async.commit_group;")
#define CP_WAIT0()  asm volatile("cp.async.wait_group 0;")
#define CP_WAIT1()  asm volatile("cp.async.wait_group 1;")

// ---------------- embed ----------------
__global__ void embed_kernel(const float* __restrict__ sparse_coords,
                             const float* __restrict__ sparse_values,
                             const float* __restrict__ query_coords,
                             const float* __restrict__ t_in,
                             const float* __restrict__ noise,
                             const float* __restrict__ B_f,
                             const float* __restrict__ Wq, const float* __restrict__ bq,
                             const float* __restrict__ Wi, const float* __restrict__ bi,
                             float* __restrict__ seq)
{
    int token = blockIdx.x;
    int b = token / NTOK;
    int n = token % NTOK;
    int tid = threadIdx.x;

    __shared__ float feat[CIN];
    const float* W; const float* bias;
    float cx, cy, val;
    if (n < NSEQ) {
        cx = sparse_coords[(b*NSEQ + n)*2 + 0];
        cy = sparse_coords[(b*NSEQ + n)*2 + 1];
        val = sparse_values[b*NSEQ + n];
        W = Wi; bias = bi;
    } else {
        int m = n - NSEQ;
        cx = query_coords[(b*NSEQ + m)*2 + 0];
        cy = query_coords[(b*NSEQ + m)*2 + 1];
        val = noise[b*NSEQ + m];
        W = Wq; bias = bq;
    }
    if (tid < NF) {
        float proj = cx * B_f[tid] + cy * B_f[NF + tid];
        feat[tid]      = sinf(proj);
        feat[NF + tid] = cosf(proj);
    }
    if (tid == 0) feat[2*NF] = val;
    __syncthreads();

    int d = tid;
    float acc = bias[d];
    const float* wrow = W + d*CIN;
    #pragma unroll
    for (int k = 0; k < CIN; k++) acc += feat[k] * wrow[k];

    float tv = t_in[b];
    float e;
    if (d < 128) e = sinf(tv * expf((float)d * (-9.210340371976184f / 127.f)));
    else         e = cosf(tv * expf((float)(d-128) * (-9.210340371976184f / 127.f)));

    seq[token*DM + d] = acc + e;
}

// ---------------- LN + Bu core ----------------
__device__ __forceinline__ void ln_bu_body(float x, int token, int tid,
                                           const float* __restrict__ lng,
                                           const float* __restrict__ lnb,
                                           const float* __restrict__ Bw,
                                           float* __restrict__ xn_out,
                                           float* __restrict__ bu_out,
                                           float* xs, float* part)
{
    int w = tid >> 5, lane = tid & 31;
    float s = x;
    #pragma unroll
    for (int o = 16; o; o >>= 1) s += __shfl_xor_sync(0xffffffffu, s, o);
    if (lane == 0) part[w] = s;
    __syncthreads();
    float mu = 0.f;
    #pragma unroll
    for (int i = 0; i < 8; i++) mu += part[i];
    mu *= (1.f/256.f);
    float dx = x - mu;
    float s2 = dx*dx;
    #pragma unroll
    for (int o = 16; o; o >>= 1) s2 += __shfl_xor_sync(0xffffffffu, s2, o);
    __syncthreads();
    if (lane == 0) part[8 + w] = s2;
    __syncthreads();
    float var = 0.f;
    #pragma unroll
    for (int i = 0; i < 8; i++) var += part[8 + i];
    var *= (1.f/256.f);

    float xn = dx * rsqrtf(var + LN_EPS) * lng[tid] + lnb[tid];
    xn_out[(size_t)token*DM + tid] = xn;
    xs[tid] = xn;
    __syncthreads();

    float bs = 0.f;
    #pragma unroll
    for (int i = 0; i < 8; i++) {
        int d = lane + i*32;
        bs += xs[d] * Bw[w*DM + d];
    }
    #pragma unroll
    for (int o = 16; o; o >>= 1) bs += __shfl_xor_sync(0xffffffffu, bs, o);
    if (lane == 0) {
        int b = token >> 11, n = token & 2047;
        bu_out[((size_t)(b*NSTATE + w))*NTOK + n] = bs;
    }
}

__global__ void ln_bu_kernel(const float* __restrict__ lng, const float* __restrict__ lnb,
                             const float* __restrict__ Bw,
                             const float* __restrict__ seq,
                             float* __restrict__ xn_out, float* __restrict__ bu_out)
{
    __shared__ float xs[DM];
    __shared__ float part[16];
    int token = blockIdx.x;
    int tid = threadIdx.x;
    float x = seq[(size_t)token*DM + tid];
    ln_bu_body(x, token, tid, lng, lnb, Bw, xn_out, bu_out, xs, part);
}

// ---------------- fused: ssm_out(l) + ln_bu(l+1) ----------------
__global__ void ssm_ln_bu_kernel(const float* __restrict__ Cw, const float* __restrict__ Dp,
                                 const float* __restrict__ xn, const float* __restrict__ hs,
                                 const float* __restrict__ gate, float* __restrict__ seq,
                                 const float* __restrict__ lng2, const float* __restrict__ lnb2,
                                 const float* __restrict__ Bw2,
                                 float* __restrict__ xn_out, float* __restrict__ bu_out)
{
    __shared__ float xs[DM];
    __shared__ float part[16];
    __shared__ float hsl[NSTATE];
    int token = blockIdx.x;
    int tid = threadIdx.x;
    if (tid < NSTATE) {
        int b = token >> 11, n = token & 2047;
        hsl[tid] = hs[((size_t)(b*NSTATE + tid))*NTOK + n];
    }
    __syncthreads();
    size_t idx = (size_t)token*DM + tid;
    float xv = xn[idx];
    float o = Dp[tid] * xv;
    #pragma unroll
    for (int s = 0; s < NSTATE; s++) o += hsl[s] * Cw[tid*NSTATE + s];
    float x = seq[idx] + gate[idx] * o;
    seq[idx] = x;
    __syncthreads();
    ln_bu_body(x, token, tid, lng2, lnb2, Bw2, xn_out, bu_out, xs, part);
}

// ---------------- last-layer ssm_out ----------------
__global__ void ssm_out_kernel(const float* __restrict__ Cw, const float* __restrict__ Dp,
                               const float* __restrict__ xn, const float* __restrict__ hs,
                               const float* __restrict__ gate, float* __restrict__ seq)
{
    int token = blockIdx.x;
    int tid = threadIdx.x;
    __shared__ float hsl[NSTATE];
    if (tid < NSTATE) {
        int b = token >> 11, n = token & 2047;
        hsl[tid] = hs[((size_t)(b*NSTATE + tid))*NTOK + n];
    }
    __syncthreads();
    size_t idx = (size_t)token*DM + tid;
    float xv = xn[idx];
    float o = Dp[tid] * xv;
    #pragma unroll
    for (int s = 0; s < NSTATE; s++) o += hsl[s] * Cw[tid*NSTATE + s];
    seq[idx] += gate[idx] * o;
}

// ---------------- scan ----------------
__global__ void scan_kernel(const float* __restrict__ A_log,
                            const float* __restrict__ bu, float* __restrict__ hs)
{
    __shared__ float sb[NTOK];
    int wi = blockIdx.x;
    int lane = threadIdx.x;
    int s = wi & 7;

    float A = -fminf(fmaxf(expf(A_log[s]), 1e-8f), 10.f);
    float Abar = expf(A * (1.f/2048.f));
    float p64  = expf(A * (1.f/32.f));

    const float* bup = bu + (size_t)wi*NTOK;
    float* hsp = hs + (size_t)wi*NTOK;

    #pragma unroll
    for (int i = 0; i < 64; i++) sb[lane + i*32] = bup[lane + i*32];
    __syncwarp();

    int base = lane * 64;
    float loc = 0.f;
    #pragma unroll 8
    for (int i = 0; i < 64; i++) loc = Abar*loc + sb[base + i];

    float aa = p64, bb = loc;
    #pragma unroll
    for (int off = 1; off < 32; off <<= 1) {
        float pa = __shfl_up_sync(0xffffffffu, aa, off);
        float pb = __shfl_up_sync(0xffffffffu, bb, off);
        if (lane >= off) { bb = aa*pb + bb; aa = aa*pa; }
    }
    float hin = __shfl_up_sync(0xffffffffu, bb, 1);
    if (lane == 0) hin = 0.f;

    float h = hin;
    #pragma unroll 8
    for (int i = 0; i < 64; i++) {
        h = Abar*h + sb[base + i];
        sb[base + i] = h;
    }
    __syncwarp();
    #pragma unroll
    for (int i = 0; i < 64; i++) hsp[lane + i*32] = sb[lane + i*32];
}

// ---------------- tensor-core GEMM (tf32x3, raw-f32 smem) ----------------
// block 128x128, K chunks of 16, 8 warps of 32(m)x64(n)
// act: 0=none 1=sigmoid 2=relu 3=relu+dot(w2)->atomicAdd C (C treated as [M])
#define GSK 20
__global__ __launch_bounds__(256, 2)
void gemm_tc(const float* __restrict__ A, const float* __restrict__ W,
             const float* __restrict__ bias, float* __restrict__ C,
             const float* __restrict__ w2,
             int rpb, int tstride, int rowoff, int act)
{
    __shared__ float As[2][128*GSK];
    __shared__ float Bs[2][128*GSK];

    int tid = threadIdx.x;
    int m0 = blockIdx.y * 128, n0 = blockIdx.x * 128;

    int r  = tid >> 1;
    int cb = (tid & 1) * 8;
    int m = m0 + r;
    int tok = (m / rpb) * tstride + rowoff + (m % rpb);
    const float* Aptr = A + (size_t)tok*DM + cb;
    const float* Bptr = W + (size_t)(n0 + r)*DM + cb;

    int w = tid >> 5, lane = tid & 31;
    int g = lane >> 2, t = lane & 3;
    int wm = w >> 1, wn = w & 1;

    float acc[2][8][4] = {};

    // first chunk
    {
        float4 a0 = *(const float4*)Aptr;
        float4 a1 = *(const float4*)(Aptr + 4);
        float4 b0 = *(const float4*)Bptr;
        float4 b1 = *(const float4*)(Bptr + 4);
        *(float4*)&As[0][r*GSK + cb]     = a0;
        *(float4*)&As[0][r*GSK + cb + 4] = a1;
        *(float4*)&Bs[0][r*GSK + cb]     = b0;
        *(float4*)&Bs[0][r*GSK + cb + 4] = b1;
    }
    __syncthreads();

    #pragma unroll 1
    for (int ck = 0; ck < 16; ck++) {
        int buf = ck & 1;
        float4 a0, a1, b0, b1;
        if (ck < 15) {
            a0 = *(const float4*)(Aptr + (ck+1)*16);
            a1 = *(const float4*)(Aptr + (ck+1)*16 + 4);
            b0 = *(const float4*)(Bptr + (ck+1)*16);
            b1 = *(const float4*)(Bptr + (ck+1)*16 + 4);
        }
        #pragma unroll
        for (int kk = 0; kk < 16; kk += 8) {
            // A fragments (2 m-tiles), split to hi/lo
            unsigned ah[2][4], al[2][4];
            #pragma unroll
            for (int mt = 0; mt < 2; mt++) {
                int row = wm*32 + mt*16;
                const float* p = &As[buf][(row + g)*GSK + kk + t];
                float r0 = p[0];
                float r1 = p[8*GSK];
                float r2 = p[4];
                float r3 = p[8*GSK + 4];
                ah[mt][0] = f2tf(r0); al[mt][0] = f2tf(r0 - __uint_as_float(ah[mt][0]));
                ah[mt][1] = f2tf(r1); al[mt][1] = f2tf(r1 - __uint_as_float(ah[mt][1]));
                ah[mt][2] = f2tf(r2); al[mt][2] = f2tf(r2 - __uint_as_float(ah[mt][2]));
                ah[mt][3] = f2tf(r3); al[mt][3] = f2tf(r3 - __uint_as_float(ah[mt][3]));
            }
            #pragma unroll
            for (int nt = 0; nt < 8; nt++) {
                int col = wn*64 + nt*8 + g;
                const float* p = &Bs[buf][col*GSK + kk + t];
                float r0 = p[0];
                float r1 = p[4];
                unsigned bh[2], bl[2];
                bh[0] = f2tf(r0); bl[0] = f2tf(r0 - __uint_as_float(bh[0]));
                bh[1] = f2tf(r1); bl[1] = f2tf(r1 - __uint_as_float(bh[1]));
                #pragma unroll
                for (int mt = 0; mt < 2; mt++) {
                    mma8(acc[mt][nt], ah[mt], bh);
                    mma8(acc[mt][nt], ah[mt], bl);
                    mma8(acc[mt][nt], al[mt], bh);
                }
            }
        }
        if (ck < 15) {
            int nb = buf ^ 1;
            *(float4*)&As[nb][r*GSK + cb]     = a0;
            *(float4*)&As[nb][r*GSK + cb + 4] = a1;
            *(float4*)&Bs[nb][r*GSK + cb]     = b0;
            *(float4*)&Bs[nb][r*GSK + cb + 4] = b1;
            __syncthreads();
        }
    }

    if (act == 3) {
        // relu + dot with w2, reduce over t-quad, atomicAdd per row
        #pragma unroll
        for (int mt = 0; mt < 2; mt++) {
            float p0 = 0.f, p1 = 0.f;
            #pragma unroll
            for (int nt = 0; nt < 8; nt++) {
                int col = n0 + wn*64 + nt*8 + t*2;
                float b0 = bias[col], b1 = bias[col+1];
                float w0 = w2[col],  w1 = w2[col+1];
                p0 += fmaxf(acc[mt][nt][0] + b0, 0.f)*w0 + fmaxf(acc[mt][nt][1] + b1, 0.f)*w1;
                p1 += fmaxf(acc[mt][nt][2] + b0, 0.f)*w0 + fmaxf(acc[mt][nt][3] + b1, 0.f)*w1;
            }
            p0 += __shfl_xor_sync(0xffffffffu, p0, 1);
            p0 += __shfl_xor_sync(0xffffffffu, p0, 2);
            p1 += __shfl_xor_sync(0xffffffffu, p1, 1);
            p1 += __shfl_xor_sync(0xffffffffu, p1, 2);
            if (t == 0) {
                int row = m0 + wm*32 + mt*16 + g;
                atomicAdd(&C[row], p0);
                atomicAdd(&C[row + 8], p1);
            }
        }
        return;
    }

    #pragma unroll
    for (int mt = 0; mt < 2; mt++) {
        int row0 = m0 + wm*32 + mt*16 + g;
        #pragma unroll
        for (int nt = 0; nt < 8; nt++) {
            int col = n0 + wn*64 + nt*8 + t*2;
            float b0 = bias[col], b1 = bias[col+1];
            float v0 = acc[mt][nt][0] + b0;
            float v1 = acc[mt][nt][1] + b1;
            float v2 = acc[mt][nt][2] + b0;
            float v3 = acc[mt][nt][3] + b1;
            if (act == 1) {
                v0 = 1.f/(1.f+__expf(-v0)); v1 = 1.f/(1.f+__expf(-v1));
                v2 = 1.f/(1.f+__expf(-v2)); v3 = 1.f/(1.f+__expf(-v3));
            } else if (act == 2) {
                v0 = fmaxf(v0,0.f); v1 = fmaxf(v1,0.f);
                v2 = fmaxf(v2,0.f); v3 = fmaxf(v3,0.f);
            }
            *(float2*)&C[(size_t)row0*DM + col]     = make_float2(v0, v1);
            *(float2*)&C[(size_t)(row0+8)*DM + col] = make_float2(v2, v3);
        }
    }
}

// ---------------- flash attention (tf32x3 both stages, cp.async) ----------
// q-tile 64, k-tile 64, hd 64; 8 warps = 4(q) x 2(k|d); 2 CTAs/SM
#define QSS 68
#define KSS 68
#define VSS 72
#define SSS 68
#define KVSZ 4608            // max(64*68, 64*72)
#define ATT_FLOATS (2*64*QSS + 2*KVSZ + 2*64*SSS + 3*64)
#define ATT_SMEM (ATT_FLOATS*4)

__global__ __launch_bounds__(256, 2)
void attn_kernel(const float* __restrict__ Q, const float* __restrict__ Km,
                 const float* __restrict__ V, float* __restrict__ O)
{
    extern __shared__ float sm[];
    float* Qh = sm;                     // [64][QSS]
    float* Ql = Qh + 64*QSS;
    float* KV0 = Ql + 64*QSS;           // raw K or V tile, buf0 (K)
    float* KV1 = KV0 + KVSZ;            // buf1 (V)
    float* Sh = KV1 + KVSZ;             // [64][SSS]
    float* Sl = Sh + 64*SSS;
    float* mrow = Sl + 64*SSS;          // 64
    float* lrow = mrow + 64;
    float* crow = lrow + 64;

    unsigned kv0s = (unsigned)__cvta_generic_to_shared(KV0);
    unsigned kv1s = (unsigned)__cvta_generic_to_shared(KV1);

    int qb = blockIdx.x, h = blockIdx.y, b = blockIdx.z;
    int tid = threadIdx.x;
    int q0 = qb * 64;

    int w = tid >> 5, lane = tid & 31;
    int g = lane >> 2, t = lane & 3;
    int wq = w >> 1, wk = w & 1;
    int q0r = wq*16, kc0 = wk*32;

    const float* Kbase = Km + ((size_t)(b*NSEQ))*DM + h*64;
    const float* Vbase = V  + ((size_t)(b*NSEQ))*DM + h*64;

    // load + split Q tile (scaled 1/8)
    for (int i = tid; i < 64*16; i += 256) {
        int q = i >> 4, d4 = (i & 15) * 4;
        float4 v = *(const float4*)&Q[((size_t)(b*NSEQ + q0 + q))*DM + h*64 + d4];
        float f[4] = {v.x*0.125f, v.y*0.125f, v.z*0.125f, v.w*0.125f};
        #pragma unroll
        for (int j = 0; j < 4; j++) {
            unsigned hi = f2tf(f[j]);
            Qh[q*QSS + d4 + j] = __uint_as_float(hi);
            Ql[q*QSS + d4 + j] = __uint_as_float(f2tf(f[j] - __uint_as_float(hi)));
        }
    }
    if (tid < 64) { mrow[tid] = -1e30f; lrow[tid] = 0.f; }

    // prefetch K tile 0 into buf0
    #pragma unroll
    for (int i = 0; i < 4; i++) {
        int idx = tid + i*256;
        int row = idx >> 4, d4 = (idx & 15) * 4;
        cpa16(kv0s + (row*KSS + d4)*4, Kbase + (size_t)row*DM + d4);
    }
    CP_COMMIT();

    float oacc[4][4] = {};

    #pragma unroll 1
    for (int kt = 0; kt < 16; kt++) {
        // issue V(kt) into buf1
        #pragma unroll
        for (int i = 0; i < 4; i++) {
            int idx = tid + i*256;
            int row = idx >> 4, d4 = (idx & 15) * 4;
            cpa16(kv1s + (row*VSS + d4)*4, Vbase + (size_t)(kt*64 + row)*DM + d4);
        }
        CP_COMMIT();
        CP_WAIT1();          // K(kt) ready
        __syncthreads();

        // ---- S = Q K^T (x3) ----
        {
            float sacc[4][4] = {};
            #pragma unroll
            for (int dk = 0; dk < 64; dk += 8) {
                unsigned ah[4], al[4];
                {
                    const float* ph = &Qh[(q0r + g)*QSS + dk + t];
                    const float* pl = &Ql[(q0r + g)*QSS + dk + t];
                    ah[0] = __float_as_uint(ph[0]);
                    ah[1] = __float_as_uint(ph[8*QSS]);
                    ah[2] = __float_as_uint(ph[4]);
                    ah[3] = __float_as_uint(ph[8*QSS + 4]);
                    al[0] = __float_as_uint(pl[0]);
                    al[1] = __float_as_uint(pl[8*QSS]);
                    al[2] = __float_as_uint(pl[4]);
                    al[3] = __float_as_uint(pl[8*QSS + 4]);
                }
                #pragma unroll
                for (int nt = 0; nt < 4; nt++) {
                    int krow = kc0 + nt*8 + g;
                    float r0 = KV0[krow*KSS + dk + t];
                    float r1 = KV0[krow*KSS + dk + t + 4];
                    unsigned bh[2], bl[2];
                    bh[0] = f2tf(r0); bl[0] = f2tf(r0 - __uint_as_float(bh[0]));
                    bh[1] = f2tf(r1); bl[1] = f2tf(r1 - __uint_as_float(bh[1]));
                    mma8(sacc[nt], ah, bh);
                    mma8(sacc[nt], ah, bl);
                    mma8(sacc[nt], al, bh);
                }
            }
            #pragma unroll
            for (int nt = 0; nt < 4; nt++) {
                int col = kc0 + nt*8 + t*2;
                *(float2*)&Sh[(q0r + g)*SSS + col]     = make_float2(sacc[nt][0], sacc[nt][1]);
                *(float2*)&Sh[(q0r + g + 8)*SSS + col] = make_float2(sacc[nt][2], sacc[nt][3]);
            }
        }
        __syncthreads();

        // ---- online softmax: 4 threads per row; write Ph/Pl ----
        {
            int q = tid >> 2, part = tid & 3;
            int j0 = part * 16;
            float mold = mrow[q];
            float mx = mold;
            float* row = Sh + q*SSS + j0;
            #pragma unroll
            for (int j = 0; j < 16; j++) mx = fmaxf(mx, row[j]);
            mx = fmaxf(mx, __shfl_xor_sync(0xffffffffu, mx, 1));
            mx = fmaxf(mx, __shfl_xor_sync(0xffffffffu, mx, 2));
            float ssum = 0.f;
            float* rowl = Sl + q*SSS + j0;
            #pragma unroll
            for (int j = 0; j < 16; j++) {
                float p = __expf(row[j] - mx);
                ssum += p;
                unsigned ph = f2tf(p);
                row[j]  = __uint_as_float(ph);
                rowl[j] = __uint_as_float(f2tf(p - __uint_as_float(ph)));
            }
            ssum += __shfl_xor_sync(0xffffffffu, ssum, 1);
            ssum += __shfl_xor_sync(0xffffffffu, ssum, 2);
            if (part == 0) {
                float corr = __expf(mold - mx);
                lrow[q] = lrow[q]*corr + ssum;
                mrow[q] = mx;
                crow[q] = corr;
            }
        }
        __syncthreads();
        CP_WAIT0();          // V(kt) ready
        __syncthreads();

        // issue K(kt+1) into buf0
        if (kt < 15) {
            #pragma unroll
            for (int i = 0; i < 4; i++) {
                int idx = tid + i*256;
                int row = idx >> 4, d4 = (idx & 15) * 4;
                cpa16(kv0s + (row*KSS + d4)*4, Kbase + (size_t)((kt+1)*64 + row)*DM + d4);
            }
            CP_COMMIT();
        }

        // ---- O = O*corr + P V (x3) ----
        {
            float c0 = crow[q0r + g];
            float c1 = crow[q0r + g + 8];
            #pragma unroll
            for (int nt = 0; nt < 4; nt++) {
                oacc[nt][0] *= c0; oacc[nt][1] *= c0;
                oacc[nt][2] *= c1; oacc[nt][3] *= c1;
            }
            #pragma unroll
            for (int kk = 0; kk < 64; kk += 8) {
                unsigned pa[4], pl[4];
                {
                    const float* ph = &Sh[(q0r + g)*SSS + kk + t];
                    const float* pq = &Sl[(q0r + g)*SSS + kk + t];
                    pa[0] = __float_as_uint(ph[0]);
                    pa[1] = __float_as_uint(ph[8*SSS]);
                    pa[2] = __float_as_uint(ph[4]);
                    pa[3] = __float_as_uint(ph[8*SSS + 4]);
                    pl[0] = __float_as_uint(pq[0]);
                    pl[1] = __float_as_uint(pq[8*SSS]);
                    pl[2] = __float_as_uint(pq[4]);
                    pl[3] = __float_as_uint(pq[8*SSS + 4]);
                }
                #pragma unroll
                for (int nt = 0; nt < 4; nt++) {
                    int dcol = kc0 + nt*8 + g;
                    float v0 = KV1[(kk + t)*VSS + dcol];
                    float v1 = KV1[(kk + t + 4)*VSS + dcol];
                    unsigned vh[2], vl[2];
                    vh[0] = f2tf(v0); vl[0] = f2tf(v0 - __uint_as_float(vh[0]));
                    vh[1] = f2tf(v1); vl[1] = f2tf(v1 - __uint_as_float(vh[1]));
                    mma8(oacc[nt], pa, vh);
                    mma8(oacc[nt], pa, vl);
                    mma8(oacc[nt], pl, vh);
                }
            }
        }
        __syncthreads();     // all reads of buf1 done before next V issue
    }

    float inv0 = 1.f / lrow[q0r + g];
    float inv1 = 1.f / lrow[q0r + g + 8];
    #pragma unroll
    for (int nt = 0; nt < 4; nt++) {
        int col = kc0 + nt*8 + t*2;
        *(float2*)&O[((size_t)(b*NSEQ + q0 + q0r + g))*DM + h*64 + col] =
            make_float2(oacc[nt][0]*inv0, oacc[nt][1]*inv0);
        *(float2*)&O[((size_t)(b*NSEQ + q0 + q0r + g + 8))*DM + h*64 + col] =
            make_float2(oacc[nt][2]*inv1, oacc[nt][3]*inv1);
    }
}

// ---------------- out init (bias preload for fused dec) ----------------
__global__ void init_out_kernel(float* __restrict__ out, const float* __restrict__ b2)
{
    int i = blockIdx.x*256 + threadIdx.x;
    out[i] = b2[0];
}

// ---------------- host launch ----------------
extern "C" void kernel_launch(void* const* d_in, const int* in_sizes, int n_in,
                              void* d_out, int out_size)
{
    const float* sparse_coords = (const float*)d_in[0];
    const float* sparse_values = (const float*)d_in[1];
    const float* query_coords  = (const float*)d_in[2];
    const float* t_in          = (const float*)d_in[3];
    const float* noise         = (const float*)d_in[4];
    const float* B_f           = (const float*)d_in[5];
    const float* Wq_in         = (const float*)d_in[6];
    const float* bq_in         = (const float*)d_in[7];
    const float* Wi_in         = (const float*)d_in[8];
    const float* bi_in         = (const float*)d_in[9];
    const float* A_log         = (const float*)d_in[10];
    const float* Bw            = (const float*)d_in[11];
    const float* Cw            = (const float*)d_in[12];
    const float* Dp            = (const float*)d_in[13];
    const float* ln_g          = (const float*)d_in[14];
    const float* ln_b          = (const float*)d_in[15];
    const float* gate_w        = (const float*)d_in[16];
    const float* gate_b        = (const float*)d_in[17];
    const float* in_proj_w     = (const float*)d_in[18];
    const float* in_proj_b     = (const float*)d_in[19];
    const float* out_w         = (const float*)d_in[20];
    const float* out_b         = (const float*)d_in[21];
    const float* dec_w1        = (const float*)d_in[22];
    const float* dec_b1        = (const float*)d_in[23];
    const float* dec_w2        = (const float*)d_in[24];
    const float* dec_b2        = (const float*)d_in[25];
    float* out = (float*)d_out;

    float *p_seq, *p_xn, *p_gate, *p_bu, *p_hs, *p_q, *p_k, *p_v, *p_att, *p_x1;
    cudaGetSymbolAddress((void**)&p_seq, g_seq);
    cudaGetSymbolAddress((void**)&p_xn,  g_xn);
    cudaGetSymbolAddress((void**)&p_gate,g_gate);
    cudaGetSymbolAddress((void**)&p_bu,  g_bu);
    cudaGetSymbolAddress((void**)&p_hs,  g_hs);
    cudaGetSymbolAddress((void**)&p_q,   g_q);
    cudaGetSymbolAddress((void**)&p_k,   g_k);
    cudaGetSymbolAddress((void**)&p_v,   g_v);
    cudaGetSymbolAddress((void**)&p_att, g_att);
    cudaGetSymbolAddress((void**)&p_x1,  g_x1);

    cudaFuncSetAttribute(attn_kernel, cudaFuncAttributeMaxDynamicSharedMemorySize, ATT_SMEM);

    int ntok_all = BATCH*NTOK;          // 32768
    int nq_all   = BATCH*NSEQ;          // 16384
    const int BIGR = 1 << 30;

    embed_kernel<<<ntok_all, 256>>>(sparse_coords, sparse_values, query_coords, t_in,
                                    noise, B_f, Wq_in, bq_in, Wi_in, bi_in, p_seq);

    ln_bu_kernel<<<ntok_all, 256>>>(ln_g, ln_b, Bw, p_seq, p_xn, p_bu);
    for (int l = 0; l < NLAYER; l++) {
        gemm_tc<<<dim3(2, ntok_all/128), 256>>>(p_xn, gate_w + l*DM*DM, gate_b + l*DM,
                                                p_gate, nullptr, BIGR, 0, 0, 1);
        scan_kernel<<<BATCH*NSTATE, 32>>>(A_log + l*NSTATE, p_bu, p_hs);
        if (l < NLAYER-1) {
            ssm_ln_bu_kernel<<<ntok_all, 256>>>(Cw + l*DM*NSTATE, Dp + l*DM,
                                                p_xn, p_hs, p_gate, p_seq,
                                                ln_g + (l+1)*DM, ln_b + (l+1)*DM,
                                                Bw + (l+1)*NSTATE*DM,
                                                p_xn, p_bu);
        } else {
            ssm_out_kernel<<<ntok_all, 256>>>(Cw + l*DM*NSTATE, Dp + l*DM,
                                              p_xn, p_hs, p_gate, p_seq);
        }
    }

    gemm_tc<<<dim3(2, nq_all/128), 256>>>(p_seq, in_proj_w,           in_proj_b,
                                          p_q, nullptr, NSEQ, NTOK, NSEQ, 0);
    gemm_tc<<<dim3(2, nq_all/128), 256>>>(p_seq, in_proj_w + DM*DM,   in_proj_b + DM,
                                          p_k, nullptr, NSEQ, NTOK, 0, 0);
    gemm_tc<<<dim3(2, nq_all/128), 256>>>(p_seq, in_proj_w + 2*DM*DM, in_proj_b + 2*DM,
                                          p_v, nullptr, NSEQ, NTOK, 0, 0);

    attn_kernel<<<dim3(16, 4, BATCH), 256, ATT_SMEM>>>(p_q, p_k, p_v, p_att);

    gemm_tc<<<dim3(2, nq_all/128), 256>>>(p_att, out_w, out_b, p_x1, nullptr, BIGR, 0, 0, 0);

    init_out_kernel<<<nq_all/256, 256>>>(out, dec_b2);
    gemm_tc<<<dim3(2, nq_all/128), 256>>>(p_x1, dec_w1, dec_b1, out, dec_w2, BIGR, 0, 0, 3);
}

// round 5
// speedup vs baseline: 1.8841x; 1.2824x over previous
#include <cuda_runtime.h>

#define BATCH 16
#define NSEQ  1024
#define NTOK  2048
#define DM    256
#define NLAYER 4
#define NSTATE 8
#define NF    16
#define CIN   33
#define LN_EPS 1e-5f

// ---------------- scratch ----------------
__device__ float g_seq [BATCH*NTOK*DM];
__device__ float g_xn  [BATCH*NTOK*DM];
__device__ float g_gate[BATCH*NTOK*DM];
__device__ float g_bu  [BATCH*NSTATE*NTOK];
__device__ float g_hs  [BATCH*NSTATE*NTOK];
__device__ float g_q   [BATCH*NSEQ*DM];
__device__ float g_k   [BATCH*NSEQ*DM];
__device__ float g_v   [BATCH*NSEQ*DM];
__device__ float g_att [BATCH*NSEQ*DM];
__device__ float g_x1  [BATCH*NSEQ*DM];

// ---------------- bf16 split helpers ----------------
__device__ __forceinline__ unsigned packbf(float x0, float x1) {
    unsigned r;
    asm("cvt.rn.bf16x2.f32 %0, %1, %2;" : "=r"(r) : "f"(x1), "f"(x0));
    return r;
}
// split pair (x0,x1) -> hi packed + lo packed (error-compensated)
__device__ __forceinline__ void split2(float x0, float x1, unsigned& h, unsigned& l) {
    h = packbf(x0, x1);
    float h0 = __uint_as_float(h << 16);
    float h1 = __uint_as_float(h & 0xFFFF0000u);
    l = packbf(x0 - h0, x1 - h1);
}
__device__ __forceinline__ void mma16(float (&d)[4], const unsigned* a, const unsigned* b) {
    asm volatile("mma.sync.aligned.m16n8k16.row.col.f32.bf16.bf16.f32 "
        "{%0,%1,%2,%3}, {%4,%5,%6,%7}, {%8,%9}, {%0,%1,%2,%3};"
        : "+f"(d[0]), "+f"(d[1]), "+f"(d[2]), "+f"(d[3])
        : "r"(a[0]), "r"(a[1]), "r"(a[2]), "r"(a[3]), "r"(b[0]), "r"(b[1]));
}
__device__ __forceinline__ void cpa16(unsigned s, const void* g) {
    asm volatile("cp.async.cg.shared.global [%0], [%1], 16;" :: "r"(s), "l"(g));
}
#define CP_COMMIT() asm volatile("cp.async.commit_group;")
#define CP_WAIT0()  asm volatile("cp.async.wait_group 0;")
#define CP_WAIT1()  asm volatile("cp.async.wait_group 1;")

// ---------------- embed ----------------
__global__ void embed_kernel(const float* __restrict__ sparse_coords,
                             const float* __restrict__ sparse_values,
                             const float* __restrict__ query_coords,
                             const float* __restrict__ t_in,
                             const float* __restrict__ noise,
                             const float* __restrict__ B_f,
                             const float* __restrict__ Wq, const float* __restrict__ bq,
                             const float* __restrict__ Wi, const float* __restrict__ bi,
                             float* __restrict__ seq)
{
    int token = blockIdx.x;
    int b = token / NTOK;
    int n = token % NTOK;
    int tid = threadIdx.x;

    __shared__ float feat[CIN];
    const float* W; const float* bias;
    float cx, cy, val;
    if (n < NSEQ) {
        cx = sparse_coords[(b*NSEQ + n)*2 + 0];
        cy = sparse_coords[(b*NSEQ + n)*2 + 1];
        val = sparse_values[b*NSEQ + n];
        W = Wi; bias = bi;
    } else {
        int m = n - NSEQ;
        cx = query_coords[(b*NSEQ + m)*2 + 0];
        cy = query_coords[(b*NSEQ + m)*2 + 1];
        val = noise[b*NSEQ + m];
        W = Wq; bias = bq;
    }
    if (tid < NF) {
        float proj = cx * B_f[tid] + cy * B_f[NF + tid];
        feat[tid]      = sinf(proj);
        feat[NF + tid] = cosf(proj);
    }
    if (tid == 0) feat[2*NF] = val;
    __syncthreads();

    int d = tid;
    float acc = bias[d];
    const float* wrow = W + d*CIN;
    #pragma unroll
    for (int k = 0; k < CIN; k++) acc += feat[k] * wrow[k];

    float tv = t_in[b];
    float e;
    if (d < 128) e = sinf(tv * expf((float)d * (-9.210340371976184f / 127.f)));
    else         e = cosf(tv * expf((float)(d-128) * (-9.210340371976184f / 127.f)));

    seq[token*DM + d] = acc + e;
}

// ---------------- LN + Bu core ----------------
__device__ __forceinline__ void ln_bu_body(float x, int token, int tid,
                                           const float* __restrict__ lng,
                                           const float* __restrict__ lnb,
                                           const float* __restrict__ Bw,
                                           float* __restrict__ xn_out,
                                           float* __restrict__ bu_out,
                                           float* xs, float* part)
{
    int w = tid >> 5, lane = tid & 31;
    float s = x;
    #pragma unroll
    for (int o = 16; o; o >>= 1) s += __shfl_xor_sync(0xffffffffu, s, o);
    if (lane == 0) part[w] = s;
    __syncthreads();
    float mu = 0.f;
    #pragma unroll
    for (int i = 0; i < 8; i++) mu += part[i];
    mu *= (1.f/256.f);
    float dx = x - mu;
    float s2 = dx*dx;
    #pragma unroll
    for (int o = 16; o; o >>= 1) s2 += __shfl_xor_sync(0xffffffffu, s2, o);
    __syncthreads();
    if (lane == 0) part[8 + w] = s2;
    __syncthreads();
    float var = 0.f;
    #pragma unroll
    for (int i = 0; i < 8; i++) var += part[8 + i];
    var *= (1.f/256.f);

    float xn = dx * rsqrtf(var + LN_EPS) * lng[tid] + lnb[tid];
    xn_out[(size_t)token*DM + tid] = xn;
    xs[tid] = xn;
    __syncthreads();

    float bs = 0.f;
    #pragma unroll
    for (int i = 0; i < 8; i++) {
        int d = lane + i*32;
        bs += xs[d] * Bw[w*DM + d];
    }
    #pragma unroll
    for (int o = 16; o; o >>= 1) bs += __shfl_xor_sync(0xffffffffu, bs, o);
    if (lane == 0) {
        int b = token >> 11, n = token & 2047;
        bu_out[((size_t)(b*NSTATE + w))*NTOK + n] = bs;
    }
}

__global__ void ln_bu_kernel(const float* __restrict__ lng, const float* __restrict__ lnb,
                             const float* __restrict__ Bw,
                             const float* __restrict__ seq,
                             float* __restrict__ xn_out, float* __restrict__ bu_out)
{
    __shared__ float xs[DM];
    __shared__ float part[16];
    int token = blockIdx.x;
    int tid = threadIdx.x;
    float x = seq[(size_t)token*DM + tid];
    ln_bu_body(x, token, tid, lng, lnb, Bw, xn_out, bu_out, xs, part);
}

// ---------------- fused: ssm_out(l) + ln_bu(l+1) ----------------
__global__ void ssm_ln_bu_kernel(const float* __restrict__ Cw, const float* __restrict__ Dp,
                                 const float* __restrict__ xn, const float* __restrict__ hs,
                                 const float* __restrict__ gate, float* __restrict__ seq,
                                 const float* __restrict__ lng2, const float* __restrict__ lnb2,
                                 const float* __restrict__ Bw2,
                                 float* __restrict__ xn_out, float* __restrict__ bu_out)
{
    __shared__ float xs[DM];
    __shared__ float part[16];
    __shared__ float hsl[NSTATE];
    int token = blockIdx.x;
    int tid = threadIdx.x;
    if (tid < NSTATE) {
        int b = token >> 11, n = token & 2047;
        hsl[tid] = hs[((size_t)(b*NSTATE + tid))*NTOK + n];
    }
    __syncthreads();
    size_t idx = (size_t)token*DM + tid;
    float xv = xn[idx];
    float o = Dp[tid] * xv;
    #pragma unroll
    for (int s = 0; s < NSTATE; s++) o += hsl[s] * Cw[tid*NSTATE + s];
    float x = seq[idx] + gate[idx] * o;
    seq[idx] = x;
    __syncthreads();
    ln_bu_body(x, token, tid, lng2, lnb2, Bw2, xn_out, bu_out, xs, part);
}

// ---------------- last-layer ssm_out ----------------
__global__ void ssm_out_kernel(const float* __restrict__ Cw, const float* __restrict__ Dp,
                               const float* __restrict__ xn, const float* __restrict__ hs,
                               const float* __restrict__ gate, float* __restrict__ seq)
{
    int token = blockIdx.x;
    int tid = threadIdx.x;
    __shared__ float hsl[NSTATE];
    if (tid < NSTATE) {
        int b = token >> 11, n = token & 2047;
        hsl[tid] = hs[((size_t)(b*NSTATE + tid))*NTOK + n];
    }
    __syncthreads();
    size_t idx = (size_t)token*DM + tid;
    float xv = xn[idx];
    float o = Dp[tid] * xv;
    #pragma unroll
    for (int s = 0; s < NSTATE; s++) o += hsl[s] * Cw[tid*NSTATE + s];
    seq[idx] += gate[idx] * o;
}

// ---------------- scan ----------------
__global__ void scan_kernel(const float* __restrict__ A_log,
                            const float* __restrict__ bu, float* __restrict__ hs)
{
    __shared__ float sb[NTOK];
    int wi = blockIdx.x;
    int lane = threadIdx.x;
    int s = wi & 7;

    float A = -fminf(fmaxf(expf(A_log[s]), 1e-8f), 10.f);
    float Abar = expf(A * (1.f/2048.f));
    float p64  = expf(A * (1.f/32.f));

    const float* bup = bu + (size_t)wi*NTOK;
    float* hsp = hs + (size_t)wi*NTOK;

    #pragma unroll
    for (int i = 0; i < 64; i++) sb[lane + i*32] = bup[lane + i*32];
    __syncwarp();

    int base = lane * 64;
    float loc = 0.f;
    #pragma unroll 8
    for (int i = 0; i < 64; i++) loc = Abar*loc + sb[base + i];

    float aa = p64, bb = loc;
    #pragma unroll
    for (int off = 1; off < 32; off <<= 1) {
        float pa = __shfl_up_sync(0xffffffffu, aa, off);
        float pb = __shfl_up_sync(0xffffffffu, bb, off);
        if (lane >= off) { bb = aa*pb + bb; aa = aa*pa; }
    }
    float hin = __shfl_up_sync(0xffffffffu, bb, 1);
    if (lane == 0) hin = 0.f;

    float h = hin;
    #pragma unroll 8
    for (int i = 0; i < 64; i++) {
        h = Abar*h + sb[base + i];
        sb[base + i] = h;
    }
    __syncwarp();
    #pragma unroll
    for (int i = 0; i < 64; i++) hsp[lane + i*32] = sb[lane + i*32];
}

// ---------------- tensor-core GEMM (bf16x3, m16n8k16) ----------------
// block 128x128, K chunks of 16, 8 warps of 32(m)x64(n)
// act: 0=none 1=sigmoid 2=relu 3=relu+dot(w2)->atomicAdd C ([M])
#define GSK 24
__global__ __launch_bounds__(256, 2)
void gemm_tc(const float* __restrict__ A, const float* __restrict__ W,
             const float* __restrict__ bias, float* __restrict__ C,
             const float* __restrict__ w2,
             int rpb, int tstride, int rowoff, int act)
{
    __shared__ float As[2][128*GSK];
    __shared__ float Bs[2][128*GSK];

    int tid = threadIdx.x;
    int m0 = blockIdx.y * 128, n0 = blockIdx.x * 128;

    int r  = tid >> 1;
    int cb = (tid & 1) * 8;
    int m = m0 + r;
    int tok = (m / rpb) * tstride + rowoff + (m % rpb);
    const float* Aptr = A + (size_t)tok*DM + cb;
    const float* Bptr = W + (size_t)(n0 + r)*DM + cb;

    int w = tid >> 5, lane = tid & 31;
    int g = lane >> 2, t = lane & 3;
    int wm = w >> 1, wn = w & 1;

    float acc[2][8][4] = {};

    {
        float4 a0 = *(const float4*)Aptr;
        float4 a1 = *(const float4*)(Aptr + 4);
        float4 b0 = *(const float4*)Bptr;
        float4 b1 = *(const float4*)(Bptr + 4);
        *(float4*)&As[0][r*GSK + cb]     = a0;
        *(float4*)&As[0][r*GSK + cb + 4] = a1;
        *(float4*)&Bs[0][r*GSK + cb]     = b0;
        *(float4*)&Bs[0][r*GSK + cb + 4] = b1;
    }
    __syncthreads();

    #pragma unroll 1
    for (int ck = 0; ck < 16; ck++) {
        int buf = ck & 1;
        float4 a0, a1, b0, b1;
        if (ck < 15) {
            a0 = *(const float4*)(Aptr + (ck+1)*16);
            a1 = *(const float4*)(Aptr + (ck+1)*16 + 4);
            b0 = *(const float4*)(Bptr + (ck+1)*16);
            b1 = *(const float4*)(Bptr + (ck+1)*16 + 4);
        }

        // A fragments (2 m-tiles) -> bf16 hi/lo packed
        unsigned ah[2][4], al[2][4];
        #pragma unroll
        for (int mt = 0; mt < 2; mt++) {
            const float* p = &As[buf][(wm*32 + mt*16 + g)*GSK + 2*t];
            float2 x0 = *(const float2*)p;
            float2 x1 = *(const float2*)(p + 8*GSK);
            float2 x2 = *(const float2*)(p + 8);
            float2 x3 = *(const float2*)(p + 8*GSK + 8);
            split2(x0.x, x0.y, ah[mt][0], al[mt][0]);
            split2(x1.x, x1.y, ah[mt][1], al[mt][1]);
            split2(x2.x, x2.y, ah[mt][2], al[mt][2]);
            split2(x3.x, x3.y, ah[mt][3], al[mt][3]);
        }
        #pragma unroll
        for (int nt = 0; nt < 8; nt++) {
            const float* p = &Bs[buf][(wn*64 + nt*8 + g)*GSK + 2*t];
            float2 y0 = *(const float2*)p;
            float2 y1 = *(const float2*)(p + 8);
            unsigned bh[2], bl[2];
            split2(y0.x, y0.y, bh[0], bl[0]);
            split2(y1.x, y1.y, bh[1], bl[1]);
            #pragma unroll
            for (int mt = 0; mt < 2; mt++) {
                mma16(acc[mt][nt], ah[mt], bh);
                mma16(acc[mt][nt], ah[mt], bl);
                mma16(acc[mt][nt], al[mt], bh);
            }
        }

        if (ck < 15) {
            int nb = buf ^ 1;
            *(float4*)&As[nb][r*GSK + cb]     = a0;
            *(float4*)&As[nb][r*GSK + cb + 4] = a1;
            *(float4*)&Bs[nb][r*GSK + cb]     = b0;
            *(float4*)&Bs[nb][r*GSK + cb + 4] = b1;
            __syncthreads();
        }
    }

    if (act == 3) {
        #pragma unroll
        for (int mt = 0; mt < 2; mt++) {
            float p0 = 0.f, p1 = 0.f;
            #pragma unroll
            for (int nt = 0; nt < 8; nt++) {
                int col = n0 + wn*64 + nt*8 + t*2;
                float b0 = bias[col], b1 = bias[col+1];
                float w0 = w2[col],  w1 = w2[col+1];
                p0 += fmaxf(acc[mt][nt][0] + b0, 0.f)*w0 + fmaxf(acc[mt][nt][1] + b1, 0.f)*w1;
                p1 += fmaxf(acc[mt][nt][2] + b0, 0.f)*w0 + fmaxf(acc[mt][nt][3] + b1, 0.f)*w1;
            }
            p0 += __shfl_xor_sync(0xffffffffu, p0, 1);
            p0 += __shfl_xor_sync(0xffffffffu, p0, 2);
            p1 += __shfl_xor_sync(0xffffffffu, p1, 1);
            p1 += __shfl_xor_sync(0xffffffffu, p1, 2);
            if (t == 0) {
                int row = m0 + wm*32 + mt*16 + g;
                atomicAdd(&C[row], p0);
                atomicAdd(&C[row + 8], p1);
            }
        }
        return;
    }

    #pragma unroll
    for (int mt = 0; mt < 2; mt++) {
        int row0 = m0 + wm*32 + mt*16 + g;
        #pragma unroll
        for (int nt = 0; nt < 8; nt++) {
            int col = n0 + wn*64 + nt*8 + t*2;
            float b0 = bias[col], b1 = bias[col+1];
            float v0 = acc[mt][nt][0] + b0;
            float v1 = acc[mt][nt][1] + b1;
            float v2 = acc[mt][nt][2] + b0;
            float v3 = acc[mt][nt][3] + b1;
            if (act == 1) {
                v0 = 1.f/(1.f+__expf(-v0)); v1 = 1.f/(1.f+__expf(-v1));
                v2 = 1.f/(1.f+__expf(-v2)); v3 = 1.f/(1.f+__expf(-v3));
            } else if (act == 2) {
                v0 = fmaxf(v0,0.f); v1 = fmaxf(v1,0.f);
                v2 = fmaxf(v2,0.f); v3 = fmaxf(v3,0.f);
            }
            *(float2*)&C[(size_t)row0*DM + col]     = make_float2(v0, v1);
            *(float2*)&C[(size_t)(row0+8)*DM + col] = make_float2(v2, v3);
        }
    }
}

// ---------------- flash attention (bf16x3 both stages, cp.async) ----------
// q-tile 64, k-tile 64, hd 64; 8 warps = 4(q) x 2(k|d)
#define QSP 36
#define KSS 72
#define VSS 68
#define SSS 68
#define SPP 36
#define ATT_WORDS (2*64*QSP + 64*KSS + 64*VSS + 64*SSS + 2*64*SPP + 3*64)
#define ATT_SMEM (ATT_WORDS*4)

__global__ __launch_bounds__(256, 2)
void attn_kernel(const float* __restrict__ Q, const float* __restrict__ Km,
                 const float* __restrict__ V, float* __restrict__ O)
{
    extern __shared__ float sm[];
    unsigned* Qph = (unsigned*)sm;          // [64][QSP] packed bf16x2 hi
    unsigned* Qpl = Qph + 64*QSP;           // lo
    float* KV0 = (float*)(Qpl + 64*QSP);    // K tile [64][KSS]
    float* KV1 = KV0 + 64*KSS;              // V tile [64][VSS]
    float* Sh  = KV1 + 64*VSS;              // scores f32 [64][SSS]
    unsigned* Sph = (unsigned*)(Sh + 64*SSS);  // P hi [64][SPP]
    unsigned* Spl = Sph + 64*SPP;
    float* mrow = (float*)(Spl + 64*SPP);
    float* lrow = mrow + 64;
    float* crow = lrow + 64;

    unsigned kv0s = (unsigned)__cvta_generic_to_shared(KV0);
    unsigned kv1s = (unsigned)__cvta_generic_to_shared(KV1);

    int qb = blockIdx.x, h = blockIdx.y, b = blockIdx.z;
    int tid = threadIdx.x;
    int q0 = qb * 64;

    int w = tid >> 5, lane = tid & 31;
    int g = lane >> 2, t = lane & 3;
    int wq = w >> 1, wk = w & 1;
    int q0r = wq*16, kc0 = wk*32;

    const float* Kbase = Km + ((size_t)(b*NSEQ))*DM + h*64;
    const float* Vbase = V  + ((size_t)(b*NSEQ))*DM + h*64;

    // load + split Q tile (scaled 1/8) into packed hi/lo
    for (int i = tid; i < 64*16; i += 256) {
        int q = i >> 4, d4 = (i & 15) * 4;
        float4 v = *(const float4*)&Q[((size_t)(b*NSEQ + q0 + q))*DM + h*64 + d4];
        unsigned h0, l0, h1, l1;
        split2(v.x*0.125f, v.y*0.125f, h0, l0);
        split2(v.z*0.125f, v.w*0.125f, h1, l1);
        int pi = q*QSP + (d4 >> 1);
        Qph[pi] = h0; Qph[pi+1] = h1;
        Qpl[pi] = l0; Qpl[pi+1] = l1;
    }
    if (tid < 64) { mrow[tid] = -1e30f; lrow[tid] = 0.f; }

    // prefetch K tile 0
    #pragma unroll
    for (int i = 0; i < 4; i++) {
        int idx = tid + i*256;
        int row = idx >> 4, d4 = (idx & 15) * 4;
        cpa16(kv0s + (row*KSS + d4)*4, Kbase + (size_t)row*DM + d4);
    }
    CP_COMMIT();

    float oacc[4][4] = {};

    #pragma unroll 1
    for (int kt = 0; kt < 16; kt++) {
        // issue V(kt)
        #pragma unroll
        for (int i = 0; i < 4; i++) {
            int idx = tid + i*256;
            int row = idx >> 4, d4 = (idx & 15) * 4;
            cpa16(kv1s + (row*VSS + d4)*4, Vbase + (size_t)(kt*64 + row)*DM + d4);
        }
        CP_COMMIT();
        CP_WAIT1();          // K(kt) ready
        __syncthreads();

        // ---- S = Q K^T (bf16x3) ----
        {
            float sacc[4][4] = {};
            #pragma unroll
            for (int dk = 0; dk < 64; dk += 16) {
                int kp = dk >> 1;
                unsigned qa[4], ql[4];
                {
                    const unsigned* ph = &Qph[(q0r + g)*QSP + kp + t];
                    const unsigned* pl = &Qpl[(q0r + g)*QSP + kp + t];
                    qa[0] = ph[0]; qa[1] = ph[8*QSP]; qa[2] = ph[4]; qa[3] = ph[8*QSP + 4];
                    ql[0] = pl[0]; ql[1] = pl[8*QSP]; ql[2] = pl[4]; ql[3] = pl[8*QSP + 4];
                }
                #pragma unroll
                for (int nt = 0; nt < 4; nt++) {
                    const float* p = &KV0[(kc0 + nt*8 + g)*KSS + dk + 2*t];
                    float2 y0 = *(const float2*)p;
                    float2 y1 = *(const float2*)(p + 8);
                    unsigned bh[2], bl[2];
                    split2(y0.x, y0.y, bh[0], bl[0]);
                    split2(y1.x, y1.y, bh[1], bl[1]);
                    mma16(sacc[nt], qa, bh);
                    mma16(sacc[nt], qa, bl);
                    mma16(sacc[nt], ql, bh);
                }
            }
            #pragma unroll
            for (int nt = 0; nt < 4; nt++) {
                int col = kc0 + nt*8 + t*2;
                *(float2*)&Sh[(q0r + g)*SSS + col]     = make_float2(sacc[nt][0], sacc[nt][1]);
                *(float2*)&Sh[(q0r + g + 8)*SSS + col] = make_float2(sacc[nt][2], sacc[nt][3]);
            }
        }
        __syncthreads();

        // ---- online softmax; write packed P hi/lo ----
        {
            int q = tid >> 2, part = tid & 3;
            int j0 = part * 16;
            float mold = mrow[q];
            float mx = mold;
            const float* row = Sh + q*SSS + j0;
            float pv[16];
            #pragma unroll
            for (int j = 0; j < 16; j++) { pv[j] = row[j]; mx = fmaxf(mx, pv[j]); }
            mx = fmaxf(mx, __shfl_xor_sync(0xffffffffu, mx, 1));
            mx = fmaxf(mx, __shfl_xor_sync(0xffffffffu, mx, 2));
            float ssum = 0.f;
            #pragma unroll
            for (int j = 0; j < 16; j++) { pv[j] = __expf(pv[j] - mx); ssum += pv[j]; }
            unsigned* oh = Sph + q*SPP + part*8;
            unsigned* ol = Spl + q*SPP + part*8;
            #pragma unroll
            for (int jj = 0; jj < 8; jj++) {
                unsigned hp, lp;
                split2(pv[2*jj], pv[2*jj+1], hp, lp);
                oh[jj] = hp; ol[jj] = lp;
            }
            ssum += __shfl_xor_sync(0xffffffffu, ssum, 1);
            ssum += __shfl_xor_sync(0xffffffffu, ssum, 2);
            if (part == 0) {
                float corr = __expf(mold - mx);
                lrow[q] = lrow[q]*corr + ssum;
                mrow[q] = mx;
                crow[q] = corr;
            }
        }
        __syncthreads();
        CP_WAIT0();          // V(kt) ready
        __syncthreads();

        // issue K(kt+1)
        if (kt < 15) {
            #pragma unroll
            for (int i = 0; i < 4; i++) {
                int idx = tid + i*256;
                int row = idx >> 4, d4 = (idx & 15) * 4;
                cpa16(kv0s + (row*KSS + d4)*4, Kbase + (size_t)((kt+1)*64 + row)*DM + d4);
            }
            CP_COMMIT();
        }

        // ---- O = O*corr + P V (bf16x3) ----
        {
            float c0 = crow[q0r + g];
            float c1 = crow[q0r + g + 8];
            #pragma unroll
            for (int nt = 0; nt < 4; nt++) {
                oacc[nt][0] *= c0; oacc[nt][1] *= c0;
                oacc[nt][2] *= c1; oacc[nt][3] *= c1;
            }
            #pragma unroll
            for (int kk = 0; kk < 64; kk += 16) {
                int kp = kk >> 1;
                unsigned pa[4], pl[4];
                {
                    const unsigned* ph = &Sph[(q0r + g)*SPP + kp + t];
                    const unsigned* pq = &Spl[(q0r + g)*SPP + kp + t];
                    pa[0] = ph[0]; pa[1] = ph[8*SPP]; pa[2] = ph[4]; pa[3] = ph[8*SPP + 4];
                    pl[0] = pq[0]; pl[1] = pq[8*SPP]; pl[2] = pq[4]; pl[3] = pq[8*SPP + 4];
                }
                #pragma unroll
                for (int nt = 0; nt < 4; nt++) {
                    int dcol = kc0 + nt*8 + g;
                    float v0 = KV1[(kk + 2*t)*VSS + dcol];
                    float v1 = KV1[(kk + 2*t + 1)*VSS + dcol];
                    float v2 = KV1[(kk + 2*t + 8)*VSS + dcol];
                    float v3 = KV1[(kk + 2*t + 9)*VSS + dcol];
                    unsigned vh[2], vl[2];
                    split2(v0, v1, vh[0], vl[0]);
                    split2(v2, v3, vh[1], vl[1]);
                    mma16(oacc[nt], pa, vh);
                    mma16(oacc[nt], pa, vl);
                    mma16(oacc[nt], pl, vh);
                }
            }
        }
        __syncthreads();
    }

    float inv0 = 1.f / lrow[q0r + g];
    float inv1 = 1.f / lrow[q0r + g + 8];
    #pragma unroll
    for (int nt = 0; nt < 4; nt++) {
        int col = kc0 + nt*8 + t*2;
        *(float2*)&O[((size_t)(b*NSEQ + q0 + q0r + g))*DM + h*64 + col] =
            make_float2(oacc[nt][0]*inv0, oacc[nt][1]*inv0);
        *(float2*)&O[((size_t)(b*NSEQ + q0 + q0r + g + 8))*DM + h*64 + col] =
            make_float2(oacc[nt][2]*inv1, oacc[nt][3]*inv1);
    }
}

// ---------------- out init ----------------
__global__ void init_out_kernel(float* __restrict__ out, const float* __restrict__ b2)
{
    int i = blockIdx.x*256 + threadIdx.x;
    out[i] = b2[0];
}

// ---------------- host launch ----------------
extern "C" void kernel_launch(void* const* d_in, const int* in_sizes, int n_in,
                              void* d_out, int out_size)
{
    const float* sparse_coords = (const float*)d_in[0];
    const float* sparse_values = (const float*)d_in[1];
    const float* query_coords  = (const float*)d_in[2];
    const float* t_in          = (const float*)d_in[3];
    const float* noise         = (const float*)d_in[4];
    const float* B_f           = (const float*)d_in[5];
    const float* Wq_in         = (const float*)d_in[6];
    const float* bq_in         = (const float*)d_in[7];
    const float* Wi_in         = (const float*)d_in[8];
    const float* bi_in         = (const float*)d_in[9];
    const float* A_log         = (const float*)d_in[10];
    const float* Bw            = (const float*)d_in[11];
    const float* Cw            = (const float*)d_in[12];
    const float* Dp            = (const float*)d_in[13];
    const float* ln_g          = (const float*)d_in[14];
    const float* ln_b          = (const float*)d_in[15];
    const float* gate_w        = (const float*)d_in[16];
    const float* gate_b        = (const float*)d_in[17];
    const float* in_proj_w     = (const float*)d_in[18];
    const float* in_proj_b     = (const float*)d_in[19];
    const float* out_w         = (const float*)d_in[20];
    const float* out_b         = (const float*)d_in[21];
    const float* dec_w1        = (const float*)d_in[22];
    const float* dec_b1        = (const float*)d_in[23];
    const float* dec_w2        = (const float*)d_in[24];
    const float* dec_b2        = (const float*)d_in[25];
    float* out = (float*)d_out;

    float *p_seq, *p_xn, *p_gate, *p_bu, *p_hs, *p_q, *p_k, *p_v, *p_att, *p_x1;
    cudaGetSymbolAddress((void**)&p_seq, g_seq);
    cudaGetSymbolAddress((void**)&p_xn,  g_xn);
    cudaGetSymbolAddress((void**)&p_gate,g_gate);
    cudaGetSymbolAddress((void**)&p_bu,  g_bu);
    cudaGetSymbolAddress((void**)&p_hs,  g_hs);
    cudaGetSymbolAddress((void**)&p_q,   g_q);
    cudaGetSymbolAddress((void**)&p_k,   g_k);
    cudaGetSymbolAddress((void**)&p_v,   g_v);
    cudaGetSymbolAddress((void**)&p_att, g_att);
    cudaGetSymbolAddress((void**)&p_x1,  g_x1);

    cudaFuncSetAttribute(attn_kernel, cudaFuncAttributeMaxDynamicSharedMemorySize, ATT_SMEM);

    int ntok_all = BATCH*NTOK;          // 32768
    int nq_all   = BATCH*NSEQ;          // 16384
    const int BIGR = 1 << 30;

    embed_kernel<<<ntok_all, 256>>>(sparse_coords, sparse_values, query_coords, t_in,
                                    noise, B_f, Wq_in, bq_in, Wi_in, bi_in, p_seq);

    ln_bu_kernel<<<ntok_all, 256>>>(ln_g, ln_b, Bw, p_seq, p_xn, p_bu);
    for (int l = 0; l < NLAYER; l++) {
        gemm_tc<<<dim3(2, ntok_all/128), 256>>>(p_xn, gate_w + l*DM*DM, gate_b + l*DM,
                                                p_gate, nullptr, BIGR, 0, 0, 1);
        scan_kernel<<<BATCH*NSTATE, 32>>>(A_log + l*NSTATE, p_bu, p_hs);
        if (l < NLAYER-1) {
            ssm_ln_bu_kernel<<<ntok_all, 256>>>(Cw + l*DM*NSTATE, Dp + l*DM,
                                                p_xn, p_hs, p_gate, p_seq,
                                                ln_g + (l+1)*DM, ln_b + (l+1)*DM,
                                                Bw + (l+1)*NSTATE*DM,
                                                p_xn, p_bu);
        } else {
            ssm_out_kernel<<<ntok_all, 256>>>(Cw + l*DM*NSTATE, Dp + l*DM,
                                              p_xn, p_hs, p_gate, p_seq);
        }
    }

    gemm_tc<<<dim3(2, nq_all/128), 256>>>(p_seq, in_proj_w,           in_proj_b,
                                          p_q, nullptr, NSEQ, NTOK, NSEQ, 0);
    gemm_tc<<<dim3(2, nq_all/128), 256>>>(p_seq, in_proj_w + DM*DM,   in_proj_b + DM,
                                          p_k, nullptr, NSEQ, NTOK, 0, 0);
    gemm_tc<<<dim3(2, nq_all/128), 256>>>(p_seq, in_proj_w + 2*DM*DM, in_proj_b + 2*DM,
                                          p_v, nullptr, NSEQ, NTOK, 0, 0);

    attn_kernel<<<dim3(16, 4, BATCH), 256, ATT_SMEM>>>(p_q, p_k, p_v, p_att);

    gemm_tc<<<dim3(2, nq_all/128), 256>>>(p_att, out_w, out_b, p_x1, nullptr, BIGR, 0, 0, 0);

    init_out_kernel<<<nq_all/256, 256>>>(out, dec_b2);
    gemm_tc<<<dim3(2, nq_all/128), 256>>>(p_x1, dec_w1, dec_b1, out, dec_w2, BIGR, 0, 0, 3);
}